// round 2
// baseline (speedup 1.0000x reference)
#include <cuda_runtime.h>

// GenerateNodes: out[m,o,k] = sum_c mix[m,c] * W[k,o,c] + b[k,o]
//   m in [0,16384), mix = concat(x[m,0:3200], seeds[m,0:15]), j = k*3+o in [0,60)
// FMA2 (packed f32x2) register-blocked kernel. Deterministic, single launch.

#define NROWS   16384
#define KX      3200
#define KS      15
#define KTOT    3215
#define JDIM    60      // 20 nodes * 3 channels
#define ROWS_PC 32      // rows per CTA
#define CHUNK   64      // c-columns per CTA chunk
#define WCH     16      // c-columns per warp per chunk
#define NCHUNK  50      // 3200 / 64
#define XS_STR  33      // padded row stride for transposed x tile

typedef unsigned long long ull;

__device__ __forceinline__ ull fma2(ull a, ull b, ull c) {
    ull d;
    asm("fma.rn.f32x2 %0, %1, %2, %3;" : "=l"(d) : "l"(a), "l"(b), "l"(c));
    return d;
}
__device__ __forceinline__ ull pack2(float lo, float hi) {
    ull d;
    asm("mov.b64 %0, {%1, %2};" : "=l"(d) : "f"(lo), "f"(hi));
    return d;
}
__device__ __forceinline__ float2 unpack2(ull v) {
    float2 r;
    asm("mov.b64 {%0, %1}, %2;" : "=f"(r.x), "=f"(r.y) : "l"(v));
    return r;
}

__global__ __launch_bounds__(128)
void gen_nodes_kernel(const float* __restrict__ x,
                      const float* __restrict__ seeds,
                      const float* __restrict__ W,
                      const float* __restrict__ b,
                      float* __restrict__ out)
{
    // smem: xs (transposed x tile) | ws (transposed W tile). red aliases xs.
    __shared__ float smem[CHUNK * XS_STR + CHUNK * JDIM];
    float* xs = smem;                       // [CHUNK][XS_STR] -> xs[c][row]
    float* ws = smem + CHUNK * XS_STR;      // [CHUNK][JDIM]   -> ws[c][j]
    float* red = smem;                      // [ROWS_PC][JDIM], 1920 <= 2112 floats

    const int tid  = threadIdx.x;
    const int lane = tid & 31;
    const int warp = tid >> 5;
    const int row0 = blockIdx.x * ROWS_PC;

    ull acc[JDIM / 2];
    #pragma unroll
    for (int i = 0; i < JDIM / 2; i++) acc[i] = 0ull;

    for (int ch = 0; ch <= NCHUNK; ch++) {
        const int cbase = ch * CHUNK;
        const int width = (ch < NCHUNK) ? CHUNK : KS;

        __syncthreads();  // smem reuse guard vs previous chunk's compute

        // ---- load x/seeds tile, transposed to xs[c_local][row] ----
        if (ch < NCHUNK) {
            #pragma unroll
            for (int i = 0; i < 4; i++) {
                int idx = tid + i * 128;            // 0..511 float4s
                int r   = idx >> 4;                 // row 0..31
                int cq  = idx & 15;                 // float4 index within 64 c's
                const float4 v = *reinterpret_cast<const float4*>(
                    x + (size_t)(row0 + r) * KX + cbase + 4 * cq);
                xs[(4 * cq + 0) * XS_STR + r] = v.x;
                xs[(4 * cq + 1) * XS_STR + r] = v.y;
                xs[(4 * cq + 2) * XS_STR + r] = v.z;
                xs[(4 * cq + 3) * XS_STR + r] = v.w;
            }
        } else {
            for (int idx = tid; idx < ROWS_PC * KS; idx += 128) {
                int r = idx / KS, c = idx - r * KS;
                xs[c * XS_STR + r] = seeds[(size_t)(row0 + r) * KS + c];
            }
        }

        // ---- load W tile, transposed to ws[c_local][j] ----
        for (int idx = tid; idx < width * JDIM; idx += 128) {
            int j = idx / width, cl = idx - j * width;
            ws[cl * JDIM + j] = W[(size_t)j * KTOT + cbase + cl];
        }

        __syncthreads();

        // ---- compute: warp handles its c sub-range of this chunk ----
        int k0, k1;
        if (ch < NCHUNK) { k0 = warp * WCH; k1 = k0 + WCH; }
        else             { k0 = warp * 4;   k1 = (k0 + 4 < KS) ? (k0 + 4) : KS; }

        #pragma unroll 4
        for (int cl = k0; cl < k1; cl++) {
            const float m = xs[cl * XS_STR + lane];
            const ull  mm = pack2(m, m);
            const ulonglong2* wrow =
                reinterpret_cast<const ulonglong2*>(&ws[cl * JDIM]);
            #pragma unroll
            for (int q = 0; q < 15; q++) {
                ulonglong2 wv = wrow[q];   // LDS.128 broadcast: w[4q..4q+3]
                acc[2 * q]     = fma2(mm, wv.x, acc[2 * q]);
                acc[2 * q + 1] = fma2(mm, wv.y, acc[2 * q + 1]);
            }
        }
    }

    // ---- deterministic cross-warp reduction into smem ----
    __syncthreads();
    for (int w = 0; w < 4; w++) {
        if (warp == w) {
            #pragma unroll
            for (int q = 0; q < JDIM / 2; q++) {
                float2 v = unpack2(acc[q]);
                float2* p = reinterpret_cast<float2*>(&red[lane * JDIM + 2 * q]);
                if (w == 0) {
                    *p = v;
                } else {
                    float2 old = *p;
                    old.x += v.x; old.y += v.y;
                    *p = old;
                }
            }
        }
        __syncthreads();
    }

    // ---- fused bias + [o,node] permute, fully coalesced store ----
    const size_t obase = (size_t)row0 * JDIM;
    for (int idx = tid; idx < ROWS_PC * JDIM; idx += 128) {
        int r    = idx / JDIM;
        int pos  = idx - r * JDIM;        // = o*20 + node
        int o    = pos / 20;
        int node = pos - o * 20;
        int j    = node * 3 + o;          // W/bias row index
        out[obase + idx] = red[r * JDIM + j] + b[j];
    }
}

extern "C" void kernel_launch(void* const* d_in, const int* in_sizes, int n_in,
                              void* d_out, int out_size)
{
    const float* x     = (const float*)d_in[0];
    const float* seeds = (const float*)d_in[1];
    const float* W     = (const float*)d_in[2];
    const float* b     = (const float*)d_in[3];
    float*       out   = (float*)d_out;

    gen_nodes_kernel<<<NROWS / ROWS_PC, 128>>>(x, seeds, W, b, out);
}

// round 4
// speedup vs baseline: 2.1503x; 2.1503x over previous
#include <cuda_runtime.h>

// GenerateNodes: out[m, o*20+node] = sum_c mix[m,c] * W[node*3+o, c] + b[node*3+o]
//   m in [0,16384), mix = concat(x[m,0:3200], seeds[m,0:15])
// Split-K=2 register-blocked FFMA2 GEMM:
//   kernel 1: transpose W -> g_Wt[c][64] (j padded to 64 with zeros)
//   kernel 2: grid 512 = 256 row-tiles x 2 K-halves; thread tile 4 rows x 8 j
//   kernel 3: reduce partials + bias + [o,node] permute

#define NROWS   16384
#define KX      3200
#define KS      15
#define KTOT    3215
#define JDIM    60
#define JPAD    64
#define MT      64      // rows per CTA
#define KC      64      // c per chunk
#define STR     68      // padded smem c-row stride (floats)
#define NCH_H   25      // chunks per K-half (25*64 = 1600)

typedef unsigned long long ull;

__device__ float g_Wt[KTOT * JPAD];          // W transposed: [c][j], zero-padded j
__device__ float g_part[2][NROWS][JPAD];     // split-K partial sums

__device__ __forceinline__ ull fma2(ull a, ull b, ull c) {
    ull d;
    asm("fma.rn.f32x2 %0, %1, %2, %3;" : "=l"(d) : "l"(a), "l"(b), "l"(c));
    return d;
}
__device__ __forceinline__ ull pack2(float lo, float hi) {
    ull d;
    asm("mov.b64 %0, {%1, %2};" : "=l"(d) : "f"(lo), "f"(hi));
    return d;
}

// ---------------- kernel 1: W transpose ----------------
__global__ void transpose_W_kernel(const float* __restrict__ W)
{
    int idx = blockIdx.x * 256 + threadIdx.x;    // idx = c*64 + j
    if (idx < KTOT * JPAD) {
        int c = idx >> 6;
        int j = idx & 63;
        g_Wt[idx] = (j < JDIM) ? W[(size_t)j * KTOT + c] : 0.0f;
    }
}

// ---------------- kernel 2: main GEMM (one K-half per CTA) ----------------
__global__ __launch_bounds__(128)
void gemm_half_kernel(const float* __restrict__ x,
                      const float* __restrict__ seeds)
{
    __shared__ float xs[KC * STR];   // transposed mix tile: xs[c][row]
    __shared__ float ws[KC * STR];   // W tile:             ws[c][j]

    const int tid  = threadIdx.x;
    const int mt   = tid & 15;       // row-group id: rows 4mt..4mt+3
    const int jt   = tid >> 4;       // j-group id:   j 8jt..8jt+7
    const int bz   = blockIdx.x >> 8;     // K-half 0/1
    const int mb   = blockIdx.x & 255;    // row tile
    const int row0 = mb * MT;
    const int lane = tid & 31;
    const int wrp  = tid >> 5;
    const int rlo  = lane >> 2;      // 0..7
    const int cqlo = lane & 3;       // 0..3

    ull acc[4][4];
    #pragma unroll
    for (int r = 0; r < 4; r++)
        #pragma unroll
        for (int q = 0; q < 4; q++) acc[r][q] = 0ull;

    const float* xp = xs + 4 * mt;
    const float* wp = ws + 8 * jt;

    #define BODY(c_) { \
        const float4 a = *reinterpret_cast<const float4*>(xp + (c_) * STR); \
        const ulonglong2 wv0 = *reinterpret_cast<const ulonglong2*>(wp + (c_) * STR); \
        const ulonglong2 wv1 = *reinterpret_cast<const ulonglong2*>(wp + (c_) * STR + 4); \
        ull m; \
        m = pack2(a.x, a.x); \
        acc[0][0] = fma2(m, wv0.x, acc[0][0]); acc[0][1] = fma2(m, wv0.y, acc[0][1]); \
        acc[0][2] = fma2(m, wv1.x, acc[0][2]); acc[0][3] = fma2(m, wv1.y, acc[0][3]); \
        m = pack2(a.y, a.y); \
        acc[1][0] = fma2(m, wv0.x, acc[1][0]); acc[1][1] = fma2(m, wv0.y, acc[1][1]); \
        acc[1][2] = fma2(m, wv1.x, acc[1][2]); acc[1][3] = fma2(m, wv1.y, acc[1][3]); \
        m = pack2(a.z, a.z); \
        acc[2][0] = fma2(m, wv0.x, acc[2][0]); acc[2][1] = fma2(m, wv0.y, acc[2][1]); \
        acc[2][2] = fma2(m, wv1.x, acc[2][2]); acc[2][3] = fma2(m, wv1.y, acc[2][3]); \
        m = pack2(a.w, a.w); \
        acc[3][0] = fma2(m, wv0.x, acc[3][0]); acc[3][1] = fma2(m, wv0.y, acc[3][1]); \
        acc[3][2] = fma2(m, wv1.x, acc[3][2]); acc[3][3] = fma2(m, wv1.y, acc[3][3]); \
    }

    const int ch0 = bz * NCH_H;
    for (int ch = ch0; ch < ch0 + NCH_H; ch++) {
        const int cbase = ch * KC;

        __syncthreads();   // protect smem from previous chunk's readers

        // ---- mix tile: 64 rows x 64 c, transposed store (2-way STS) ----
        #pragma unroll
        for (int i = 0; i < 8; i++) {
            const int r  = rlo + 8 * wrp + 32 * (i >> 2);    // 0..63
            const int cq = cqlo + 4 * (i & 3);               // 0..15
            const float4 v = *reinterpret_cast<const float4*>(
                x + (size_t)(row0 + r) * KX + cbase + 4 * cq);
            xs[(4 * cq + 0) * STR + r] = v.x;
            xs[(4 * cq + 1) * STR + r] = v.y;
            xs[(4 * cq + 2) * STR + r] = v.z;
            xs[(4 * cq + 3) * STR + r] = v.w;
        }
        // ---- W tile: coalesced float4 copy from pre-transposed g_Wt ----
        #pragma unroll
        for (int i = 0; i < 8; i++) {
            const int idx = tid + i * 128;     // 0..1023
            const int cl  = idx >> 4;
            const int jq  = idx & 15;
            *reinterpret_cast<float4*>(&ws[cl * STR + 4 * jq]) =
                *reinterpret_cast<const float4*>(&g_Wt[(size_t)(cbase + cl) * JPAD + 4 * jq]);
        }

        __syncthreads();

        #pragma unroll 4
        for (int c = 0; c < KC; c++) BODY(c)
    }

    // ---- seeds remainder (15 c's), K-half 1 only ----
    if (bz == 1) {
        __syncthreads();
        for (int idx = tid; idx < MT * KS; idx += 128) {
            const int r  = idx / KS;
            const int cl = idx - r * KS;
            xs[cl * STR + r] = seeds[(size_t)(row0 + r) * KS + cl];
        }
        for (int idx = tid; idx < KS * 16; idx += 128) {    // 240 float4
            const int cl = idx >> 4;
            const int jq = idx & 15;
            *reinterpret_cast<float4*>(&ws[cl * STR + 4 * jq]) =
                *reinterpret_cast<const float4*>(&g_Wt[(size_t)(KX + cl) * JPAD + 4 * jq]);
        }
        __syncthreads();
        for (int c = 0; c < KS; c++) BODY(c)
    }
    #undef BODY

    // ---- store partials (no cross-thread reduction needed) ----
    #pragma unroll
    for (int rr = 0; rr < 4; rr++) {
        ulonglong2* dst = reinterpret_cast<ulonglong2*>(
            &g_part[bz][row0 + 4 * mt + rr][8 * jt]);
        dst[0] = make_ulonglong2(acc[rr][0], acc[rr][1]);
        dst[1] = make_ulonglong2(acc[rr][2], acc[rr][3]);
    }
}

// ---------------- kernel 3: reduce + bias + permute ----------------
__global__ void reduce_kernel(const float* __restrict__ b, float* __restrict__ out)
{
    int idx = blockIdx.x * 256 + threadIdx.x;
    if (idx >= NROWS * JDIM) return;
    const int row  = idx / JDIM;
    const int pos  = idx - row * JDIM;     // = o*20 + node
    const int o    = pos / 20;
    const int node = pos - 20 * o;
    const int j    = node * 3 + o;
    out[idx] = g_part[0][row][j] + g_part[1][row][j] + b[j];
}

extern "C" void kernel_launch(void* const* d_in, const int* in_sizes, int n_in,
                              void* d_out, int out_size)
{
    const float* x     = (const float*)d_in[0];
    const float* seeds = (const float*)d_in[1];
    const float* W     = (const float*)d_in[2];
    const float* b     = (const float*)d_in[3];
    float*       out   = (float*)d_out;

    transpose_W_kernel<<<(KTOT * JPAD + 255) / 256, 256>>>(W);
    gemm_half_kernel<<<512, 128>>>(x, seeds);
    reduce_kernel<<<(NROWS * JDIM + 255) / 256, 256>>>(b, out);
}

// round 7
// speedup vs baseline: 2.5836x; 1.2015x over previous
#include <cuda_runtime.h>
#include <cuda_bf16.h>

// GenerateNodes via bf16-split mma.sync (HMMA) GEMM — compute_103-safe.
//   out[m, o*20+node] = sum_c mix[m,c] * W[node*3+o, c] + b[node*3+o]
//   mix = concat(x[m,0:3200], seeds[m,0:15]); fp32 split into bf16 hi+lo,
//   D = Ahi*Bhi + Ahi*Blo + Alo*Bhi accumulated in fp32 registers.

#define NROWS   16384
#define KX      3200
#define KS      15
#define KTOT    3215
#define KPAD    3264      // 51 * 64
#define JDIM    60
#define JPAD    64
#define MT      128       // rows per CTA
#define THREADS 256

#define A_BYTES (MT * 128)        // 16384: 128 rows x 64 bf16 (128 B, SW128)
#define B_BYTES (JPAD * 128)      // 8192
#define STG     (2 * A_BYTES + 2 * B_BYTES)   // 49152 per stage
#define OFF_AHI(s) ((s) * STG)
#define OFF_ALO(s) ((s) * STG + A_BYTES)
#define OFF_BHI(s) ((s) * STG + 2 * A_BYTES)
#define OFF_BLO(s) ((s) * STG + 2 * A_BYTES + B_BYTES)
#define SMEM_SZ    (2 * STG)      // 98304 bytes

__device__ __align__(16) __nv_bfloat16 g_Whi[JPAD * KPAD];
__device__ __align__(16) __nv_bfloat16 g_Wlo[JPAD * KPAD];

// ------------------------- helpers -------------------------
__device__ __forceinline__ unsigned s2u(const void* p) {
    unsigned a;
    asm("{ .reg .u64 t; cvta.to.shared.u64 t, %1; cvt.u32.u64 %0, t; }"
        : "=r"(a) : "l"(p));
    return a;
}
__device__ __forceinline__ unsigned swz(unsigned off) {
    return off ^ ((off >> 3) & 0x70);
}
__device__ __forceinline__ unsigned pack_hi(float a, float b) {
    unsigned short ra = __bfloat16_as_ushort(__float2bfloat16_rn(a));
    unsigned short rb = __bfloat16_as_ushort(__float2bfloat16_rn(b));
    return (unsigned)ra | ((unsigned)rb << 16);
}
__device__ __forceinline__ void ldsm4(unsigned addr, unsigned& r0, unsigned& r1,
                                      unsigned& r2, unsigned& r3) {
    asm volatile("ldmatrix.sync.aligned.m8n8.x4.shared.b16 {%0,%1,%2,%3}, [%4];"
                 : "=r"(r0), "=r"(r1), "=r"(r2), "=r"(r3) : "r"(addr));
}
__device__ __forceinline__ void mmabf16(float* c, unsigned a0, unsigned a1,
                                        unsigned a2, unsigned a3,
                                        unsigned b0, unsigned b1) {
    asm volatile(
        "mma.sync.aligned.m16n8k16.row.col.f32.bf16.bf16.f32 "
        "{%0,%1,%2,%3}, {%4,%5,%6,%7}, {%8,%9}, {%0,%1,%2,%3};"
        : "+f"(c[0]), "+f"(c[1]), "+f"(c[2]), "+f"(c[3])
        : "r"(a0), "r"(a1), "r"(a2), "r"(a3), "r"(b0), "r"(b1));
}

// ------------------ kernel 1: split W into bf16 hi/lo ------------------
__global__ void prep_W_kernel(const float* __restrict__ W) {
    int idx = blockIdx.x * 256 + threadIdx.x;
    if (idx >= JPAD * KPAD) return;
    int j = idx / KPAD;
    int c = idx - j * KPAD;
    float v = (j < JDIM && c < KTOT) ? W[(size_t)j * KTOT + c] : 0.0f;
    __nv_bfloat16 hi = __float2bfloat16_rn(v);
    g_Whi[idx] = hi;
    g_Wlo[idx] = __float2bfloat16_rn(v - __bfloat162float(hi));
}

// ------------------------- main GEMM kernel -------------------------
__global__ __launch_bounds__(THREADS)
void mma_kernel(const float* __restrict__ x, const float* __restrict__ seeds,
                const float* __restrict__ bias, float* __restrict__ out)
{
    extern __shared__ char smem[];
    const unsigned sb = s2u(smem);
    const int tid  = threadIdx.x;
    const int lane = tid & 31;
    const int warp = tid >> 5;            // 8 warps; warp owns rows 16w..16w+15
    const int row0 = blockIdx.x * MT;

    // ldmatrix lane geometry
    const int amat  = lane >> 3;
    const int arow  = 16 * warp + 8 * (amat & 1) + (lane & 7);
    const int acolb = (amat >> 1) * 16;              // byte offset within k16
    const int brow  = (lane & 7);
    const int bnt   = (lane >> 4) & 1;               // ntile within pair
    const int bkb   = ((lane >> 3) & 1) * 16;        // byte k-offset

    // gmem->smem thread mappings (same as previous rounds)
    const int xr_r[8] = { (tid       ) >> 4, (tid +  256) >> 4, (tid +  512) >> 4, (tid +  768) >> 4,
                          (tid + 1024) >> 4, (tid + 1280) >> 4, (tid + 1536) >> 4, (tid + 1792) >> 4 };
    const int xq  = tid & 15;
    const int wj0 = tid >> 3, wj1 = (tid + 256) >> 3;
    const int wqq = tid & 7;

    float acc[8][4];
    #pragma unroll
    for (int n = 0; n < 8; n++)
        #pragma unroll
        for (int q = 0; q < 4; q++) acc[n][q] = 0.0f;

    float4 xa[8], xb[8];
    uint4  wa[4], wb[4];

    #define LOADX(buf, ch) { _Pragma("unroll") \
        for (int i = 0; i < 8; i++) \
            buf[i] = *reinterpret_cast<const float4*>( \
                x + (size_t)(row0 + xr_r[i]) * KX + (ch) * 64 + 4 * xq); }
    #define LOADW(buf, ch) { \
        buf[0] = *reinterpret_cast<const uint4*>(&g_Whi[(size_t)wj0 * KPAD + (ch) * 64 + 8 * wqq]); \
        buf[1] = *reinterpret_cast<const uint4*>(&g_Whi[(size_t)wj1 * KPAD + (ch) * 64 + 8 * wqq]); \
        buf[2] = *reinterpret_cast<const uint4*>(&g_Wlo[(size_t)wj0 * KPAD + (ch) * 64 + 8 * wqq]); \
        buf[3] = *reinterpret_cast<const uint4*>(&g_Wlo[(size_t)wj1 * KPAD + (ch) * 64 + 8 * wqq]); }
    #define STSX(buf, s) { _Pragma("unroll") \
        for (int i = 0; i < 8; i++) { \
            const float4 v = buf[i]; \
            const unsigned off = swz((unsigned)(xr_r[i] * 128 + 8 * xq)); \
            float h0 = __bfloat162float(__float2bfloat16_rn(v.x)); \
            float h1 = __bfloat162float(__float2bfloat16_rn(v.y)); \
            float h2 = __bfloat162float(__float2bfloat16_rn(v.z)); \
            float h3 = __bfloat162float(__float2bfloat16_rn(v.w)); \
            *reinterpret_cast<unsigned*>(smem + OFF_AHI(s) + off)     = pack_hi(v.x, v.y); \
            *reinterpret_cast<unsigned*>(smem + OFF_AHI(s) + off + 4) = pack_hi(v.z, v.w); \
            *reinterpret_cast<unsigned*>(smem + OFF_ALO(s) + off)     = pack_hi(v.x - h0, v.y - h1); \
            *reinterpret_cast<unsigned*>(smem + OFF_ALO(s) + off + 4) = pack_hi(v.z - h2, v.w - h3); } }
    #define STSW(buf, s) { \
        const unsigned o0 = swz((unsigned)(wj0 * 128 + 16 * wqq)); \
        const unsigned o1 = swz((unsigned)(wj1 * 128 + 16 * wqq)); \
        *reinterpret_cast<uint4*>(smem + OFF_BHI(s) + o0) = buf[0]; \
        *reinterpret_cast<uint4*>(smem + OFF_BHI(s) + o1) = buf[1]; \
        *reinterpret_cast<uint4*>(smem + OFF_BLO(s) + o0) = buf[2]; \
        *reinterpret_cast<uint4*>(smem + OFF_BLO(s) + o1) = buf[3]; }

    #define COMPUTE(s) { \
        const unsigned ahiB = sb + OFF_AHI(s), aloB = sb + OFF_ALO(s); \
        const unsigned bhiB = sb + OFF_BHI(s), bloB = sb + OFF_BLO(s); \
        _Pragma("unroll") \
        for (int kk = 0; kk < 4; kk++) { \
            const unsigned aoff = swz((unsigned)(arow * 128 + 32 * kk + acolb)); \
            unsigned ah0, ah1, ah2, ah3, al0, al1, al2, al3; \
            ldsm4(ahiB + aoff, ah0, ah1, ah2, ah3); \
            ldsm4(aloB + aoff, al0, al1, al2, al3); \
            _Pragma("unroll") \
            for (int ntp = 0; ntp < 4; ntp++) { \
                const unsigned boff = swz((unsigned)((8 * (2 * ntp + bnt) + brow) * 128 + 32 * kk + bkb)); \
                unsigned bh0, bh1, bh2, bh3, bl0, bl1, bl2, bl3; \
                ldsm4(bhiB + boff, bh0, bh1, bh2, bh3); \
                ldsm4(bloB + boff, bl0, bl1, bl2, bl3); \
                mmabf16(acc[2 * ntp],     ah0, ah1, ah2, ah3, bh0, bh1); \
                mmabf16(acc[2 * ntp],     ah0, ah1, ah2, ah3, bl0, bl1); \
                mmabf16(acc[2 * ntp],     al0, al1, al2, al3, bh0, bh1); \
                mmabf16(acc[2 * ntp + 1], ah0, ah1, ah2, ah3, bh2, bh3); \
                mmabf16(acc[2 * ntp + 1], ah0, ah1, ah2, ah3, bl2, bl3); \
                mmabf16(acc[2 * ntp + 1], al0, al1, al2, al3, bh2, bh3); \
            } \
        } }

    LOADX(xa, 0); LOADW(wa, 0);

    for (int ch = 0; ch < 50; ch += 2) {
        // ---- even chunk -> stage 0 ----
        STSX(xa, 0); STSW(wa, 0);
        __syncthreads();
        LOADX(xb, ch + 1); LOADW(wb, ch + 1);        // ch+1 <= 49 always
        COMPUTE(0);
        // ---- odd chunk -> stage 1 ----
        STSX(xb, 1); STSW(wb, 1);
        __syncthreads();
        if (ch + 2 < 50) { LOADX(xa, ch + 2); LOADW(wa, ch + 2); }
        COMPUTE(1);
    }

    // ---- seeds chunk (ch = 50) -> stage 0 ----
    __syncthreads();                                  // drain stage-1 readers
    for (int i = tid; i < (2 * A_BYTES) / 16; i += THREADS)
        *reinterpret_cast<uint4*>(smem + OFF_AHI(0) + 16 * i) = make_uint4(0, 0, 0, 0);
    __syncthreads();
    for (int i = tid; i < MT * KS; i += THREADS) {
        const int r = i / KS, c = i - r * KS;
        const float v = seeds[(size_t)(row0 + r) * KS + c];
        const unsigned off = swz((unsigned)(r * 128 + 2 * c));
        __nv_bfloat16 hi = __float2bfloat16_rn(v);
        *reinterpret_cast<__nv_bfloat16*>(smem + OFF_AHI(0) + off) = hi;
        *reinterpret_cast<__nv_bfloat16*>(smem + OFF_ALO(0) + off) =
            __float2bfloat16_rn(v - __bfloat162float(hi));
    }
    LOADW(wa, 50); STSW(wa, 0);
    __syncthreads();
    COMPUTE(0);

    // ---- epilogue: frags -> smem -> permuted+bias store ----
    __syncthreads();                                  // all computes done
    float* red = reinterpret_cast<float*>(smem);      // [128][68]
    const int g = lane >> 2, t = lane & 3;
    #pragma unroll
    for (int nt = 0; nt < 8; nt++) {
        red[(16 * warp + g)     * 68 + 8 * nt + 2 * t]     = acc[nt][0];
        red[(16 * warp + g)     * 68 + 8 * nt + 2 * t + 1] = acc[nt][1];
        red[(16 * warp + 8 + g) * 68 + 8 * nt + 2 * t]     = acc[nt][2];
        red[(16 * warp + 8 + g) * 68 + 8 * nt + 2 * t + 1] = acc[nt][3];
    }
    __syncthreads();
    for (int i = tid; i < MT * JDIM; i += THREADS) {
        const int r = i / JDIM, pos = i - r * JDIM;
        const int o = pos / 20, node = pos - 20 * o;
        const int j = node * 3 + o;
        out[(size_t)row0 * JDIM + i] = red[r * 68 + j] + bias[j];
    }
}

extern "C" void kernel_launch(void* const* d_in, const int* in_sizes, int n_in,
                              void* d_out, int out_size)
{
    const float* x     = (const float*)d_in[0];
    const float* seeds = (const float*)d_in[1];
    const float* W     = (const float*)d_in[2];
    const float* b     = (const float*)d_in[3];
    float*       out   = (float*)d_out;

    cudaFuncSetAttribute(mma_kernel,
                         cudaFuncAttributeMaxDynamicSharedMemorySize, SMEM_SZ);
    prep_W_kernel<<<(JPAD * KPAD + 255) / 256, 256>>>(W);
    mma_kernel<<<NROWS / MT, THREADS, SMEM_SZ>>>(x, seeds, b, out);
}

// round 8
// speedup vs baseline: 4.3463x; 1.6823x over previous
#include <cuda_runtime.h>
#include <cuda_bf16.h>

// GenerateNodes via bf16-split mma.sync (HMMA) GEMM — compute_103-safe.
//   out[m, o*20+node] = sum_c mix[m,c] * W[node*3+o, c] + b[node*3+o]
//   mix = concat(x[m,0:3200], seeds[m,0:15]); fp32 split into bf16 hi+lo,
//   D = Ahi*Bhi + Ahi*Blo + Alo*Bhi accumulated in fp32 registers.
// R7: 256 CTAs x 128 thr (MT=64, 2 CTAs/SM), cp.async W, 1 sync/chunk.

#define NROWS   16384
#define KX      3200
#define KS      15
#define KTOT    3215
#define KPAD    3264      // 51 * 64
#define JDIM    60
#define JPAD    64
#define MT      64        // rows per CTA
#define THREADS 128

#define A_BYTES (MT * 128)        // 8192: 64 rows x 64 bf16 (128 B, SW128)
#define B_BYTES (JPAD * 128)      // 8192
#define STG     (2 * A_BYTES + 2 * B_BYTES)   // 32768 per stage
#define OFF_AHI(s) ((s) * STG)
#define OFF_ALO(s) ((s) * STG + A_BYTES)
#define OFF_BHI(s) ((s) * STG + 2 * A_BYTES)
#define OFF_BLO(s) ((s) * STG + 2 * A_BYTES + B_BYTES)
#define SMEM_SZ    (2 * STG)      // 65536 bytes

__device__ __align__(16) __nv_bfloat16 g_Whi[JPAD * KPAD];
__device__ __align__(16) __nv_bfloat16 g_Wlo[JPAD * KPAD];

// ------------------------- helpers -------------------------
__device__ __forceinline__ unsigned s2u(const void* p) {
    unsigned a;
    asm("{ .reg .u64 t; cvta.to.shared.u64 t, %1; cvt.u32.u64 %0, t; }"
        : "=r"(a) : "l"(p));
    return a;
}
__device__ __forceinline__ unsigned swz(unsigned off) {
    return off ^ ((off >> 3) & 0x70);
}
__device__ __forceinline__ unsigned pack_hi(float a, float b) {
    unsigned short ra = __bfloat16_as_ushort(__float2bfloat16_rn(a));
    unsigned short rb = __bfloat16_as_ushort(__float2bfloat16_rn(b));
    return (unsigned)ra | ((unsigned)rb << 16);
}
__device__ __forceinline__ void ldsm4(unsigned addr, unsigned& r0, unsigned& r1,
                                      unsigned& r2, unsigned& r3) {
    asm volatile("ldmatrix.sync.aligned.m8n8.x4.shared.b16 {%0,%1,%2,%3}, [%4];"
                 : "=r"(r0), "=r"(r1), "=r"(r2), "=r"(r3) : "r"(addr));
}
__device__ __forceinline__ void mmabf16(float* c, unsigned a0, unsigned a1,
                                        unsigned a2, unsigned a3,
                                        unsigned b0, unsigned b1) {
    asm volatile(
        "mma.sync.aligned.m16n8k16.row.col.f32.bf16.bf16.f32 "
        "{%0,%1,%2,%3}, {%4,%5,%6,%7}, {%8,%9}, {%0,%1,%2,%3};"
        : "+f"(c[0]), "+f"(c[1]), "+f"(c[2]), "+f"(c[3])
        : "r"(a0), "r"(a1), "r"(a2), "r"(a3), "r"(b0), "r"(b1));
}
__device__ __forceinline__ void cpasync16(unsigned dst, const void* src) {
    asm volatile("cp.async.cg.shared.global [%0], [%1], 16;"
                 :: "r"(dst), "l"(src) : "memory");
}

// ------------------ kernel 1: split W into bf16 hi/lo ------------------
__global__ void prep_W_kernel(const float* __restrict__ W) {
    int idx = blockIdx.x * 256 + threadIdx.x;
    if (idx >= JPAD * KPAD) return;
    int j = idx / KPAD;
    int c = idx - j * KPAD;
    float v = (j < JDIM && c < KTOT) ? W[(size_t)j * KTOT + c] : 0.0f;
    __nv_bfloat16 hi = __float2bfloat16_rn(v);
    g_Whi[idx] = hi;
    g_Wlo[idx] = __float2bfloat16_rn(v - __bfloat162float(hi));
}

// ------------------------- main GEMM kernel -------------------------
__global__ __launch_bounds__(THREADS)
void mma_kernel(const float* __restrict__ x, const float* __restrict__ seeds,
                const float* __restrict__ bias, float* __restrict__ out)
{
    extern __shared__ char smem[];
    const unsigned sb = s2u(smem);
    const int tid  = threadIdx.x;
    const int lane = tid & 31;
    const int warp = tid >> 5;            // 4 warps; warp owns rows 16w..16w+15
    const int row0 = blockIdx.x * MT;

    // ldmatrix lane geometry
    const int amat  = lane >> 3;
    const int arow  = 16 * warp + 8 * (amat & 1) + (lane & 7);
    const int acolb = (amat >> 1) * 16;              // byte offset within k16
    const int brow  = (lane & 7);
    const int bnt   = (lane >> 4) & 1;               // ntile within pair
    const int bkb   = ((lane >> 3) & 1) * 16;        // byte k-offset

    // gmem->smem mappings: x tile = 64 rows x 64 floats = 1024 float4
    const int xr_r[8] = { (tid      ) >> 4, (tid + 128) >> 4, (tid + 256) >> 4, (tid + 384) >> 4,
                          (tid + 512) >> 4, (tid + 640) >> 4, (tid + 768) >> 4, (tid + 896) >> 4 };
    const int xq  = tid & 15;
    // W tile (per half) = 64 j x 8 chunks of 16B = 512; 4 iters of 128 thr
    const int wj[4] = { (tid) >> 3, (tid + 128) >> 3, (tid + 256) >> 3, (tid + 384) >> 3 };
    const int wqq = tid & 7;

    float acc[8][4];
    #pragma unroll
    for (int n = 0; n < 8; n++)
        #pragma unroll
        for (int q = 0; q < 4; q++) acc[n][q] = 0.0f;

    float4 xr[8];

    #define LOADX(ch) { _Pragma("unroll") \
        for (int i = 0; i < 8; i++) \
            xr[i] = *reinterpret_cast<const float4*>( \
                x + (size_t)(row0 + xr_r[i]) * KX + (ch) * 64 + 4 * xq); }
    #define CPW(ch, s) { _Pragma("unroll") \
        for (int i = 0; i < 4; i++) { \
            const unsigned so = swz((unsigned)(wj[i] * 128 + 16 * wqq)); \
            cpasync16(sb + OFF_BHI(s) + so, \
                      &g_Whi[(size_t)wj[i] * KPAD + (ch) * 64 + 8 * wqq]); \
            cpasync16(sb + OFF_BLO(s) + so, \
                      &g_Wlo[(size_t)wj[i] * KPAD + (ch) * 64 + 8 * wqq]); \
        } \
        asm volatile("cp.async.commit_group;" ::: "memory"); }
    #define STSX(s) { _Pragma("unroll") \
        for (int i = 0; i < 8; i++) { \
            const float4 v = xr[i]; \
            const unsigned off = swz((unsigned)(xr_r[i] * 128 + 8 * xq)); \
            float h0 = __bfloat162float(__float2bfloat16_rn(v.x)); \
            float h1 = __bfloat162float(__float2bfloat16_rn(v.y)); \
            float h2 = __bfloat162float(__float2bfloat16_rn(v.z)); \
            float h3 = __bfloat162float(__float2bfloat16_rn(v.w)); \
            *reinterpret_cast<unsigned*>(smem + OFF_AHI(s) + off)     = pack_hi(v.x, v.y); \
            *reinterpret_cast<unsigned*>(smem + OFF_AHI(s) + off + 4) = pack_hi(v.z, v.w); \
            *reinterpret_cast<unsigned*>(smem + OFF_ALO(s) + off)     = pack_hi(v.x - h0, v.y - h1); \
            *reinterpret_cast<unsigned*>(smem + OFF_ALO(s) + off + 4) = pack_hi(v.z - h2, v.w - h3); } }

    #define COMPUTE(s) { \
        const unsigned ahiB = sb + OFF_AHI(s), aloB = sb + OFF_ALO(s); \
        const unsigned bhiB = sb + OFF_BHI(s), bloB = sb + OFF_BLO(s); \
        _Pragma("unroll") \
        for (int kk = 0; kk < 4; kk++) { \
            const unsigned aoff = swz((unsigned)(arow * 128 + 32 * kk + acolb)); \
            unsigned ah0, ah1, ah2, ah3, al0, al1, al2, al3; \
            ldsm4(ahiB + aoff, ah0, ah1, ah2, ah3); \
            ldsm4(aloB + aoff, al0, al1, al2, al3); \
            _Pragma("unroll") \
            for (int ntp = 0; ntp < 4; ntp++) { \
                const unsigned boff = swz((unsigned)((8 * (2 * ntp + bnt) + brow) * 128 + 32 * kk + bkb)); \
                unsigned bh0, bh1, bh2, bh3, bl0, bl1, bl2, bl3; \
                ldsm4(bhiB + boff, bh0, bh1, bh2, bh3); \
                ldsm4(bloB + boff, bl0, bl1, bl2, bl3); \
                mmabf16(acc[2 * ntp],     ah0, ah1, ah2, ah3, bh0, bh1); \
                mmabf16(acc[2 * ntp],     ah0, ah1, ah2, ah3, bl0, bl1); \
                mmabf16(acc[2 * ntp],     al0, al1, al2, al3, bh0, bh1); \
                mmabf16(acc[2 * ntp + 1], ah0, ah1, ah2, ah3, bh2, bh3); \
                mmabf16(acc[2 * ntp + 1], ah0, ah1, ah2, ah3, bl2, bl3); \
                mmabf16(acc[2 * ntp + 1], al0, al1, al2, al3, bh2, bh3); \
            } \
        } }

    // ---------------- pipeline: 1 sync per chunk, ping-pong stages ----------------
    CPW(0, 0);
    LOADX(0);

    for (int ch = 0; ch < 50; ch++) {
        const int s = ch & 1;
        STSX(s);                                           // x(ch) -> stage s
        asm volatile("cp.async.wait_group 0;" ::: "memory");  // W(ch) arrived
        __syncthreads();                                   // stage s ready; s^1 free
        CPW(ch + 1, s ^ 1);                                // W(ch+1) async
        if (ch + 1 < 50) LOADX(ch + 1);                    // x(ch+1) -> regs
        COMPUTE(s);
    }

    // ---- seeds chunk (ch = 50, stage 0) ----
    // stage0 A was last read in COMPUTE(48); chunk-49's sync ordered that.
    for (int i = tid; i < (2 * A_BYTES) / 16; i += THREADS)
        *reinterpret_cast<uint4*>(smem + OFF_AHI(0) + 16 * i) = make_uint4(0, 0, 0, 0);
    __syncthreads();                                       // zeros visible
    for (int i = tid; i < MT * KS; i += THREADS) {
        const int r = i / KS, c = i - r * KS;
        const float v = seeds[(size_t)(row0 + r) * KS + c];
        const unsigned off = swz((unsigned)(r * 128 + 2 * c));
        __nv_bfloat16 hi = __float2bfloat16_rn(v);
        *reinterpret_cast<__nv_bfloat16*>(smem + OFF_AHI(0) + off) = hi;
        *reinterpret_cast<__nv_bfloat16*>(smem + OFF_ALO(0) + off) =
            __float2bfloat16_rn(v - __bfloat162float(hi));
    }
    asm volatile("cp.async.wait_group 0;" ::: "memory");   // W(50) arrived
    __syncthreads();
    COMPUTE(0);

    // ---- epilogue: frags -> smem -> permuted+bias store ----
    __syncthreads();                                       // all computes done
    float* red = reinterpret_cast<float*>(smem);           // [64][68]
    const int g = lane >> 2, t = lane & 3;
    #pragma unroll
    for (int nt = 0; nt < 8; nt++) {
        red[(16 * warp + g)     * 68 + 8 * nt + 2 * t]     = acc[nt][0];
        red[(16 * warp + g)     * 68 + 8 * nt + 2 * t + 1] = acc[nt][1];
        red[(16 * warp + 8 + g) * 68 + 8 * nt + 2 * t]     = acc[nt][2];
        red[(16 * warp + 8 + g) * 68 + 8 * nt + 2 * t + 1] = acc[nt][3];
    }
    __syncthreads();
    for (int i = tid; i < MT * JDIM; i += THREADS) {
        const int r = i / JDIM, pos = i - r * JDIM;
        const int o = pos / 20, node = pos - 20 * o;
        const int j = node * 3 + o;
        out[(size_t)row0 * JDIM + i] = red[r * 68 + j] + bias[j];
    }
}

extern "C" void kernel_launch(void* const* d_in, const int* in_sizes, int n_in,
                              void* d_out, int out_size)
{
    const float* x     = (const float*)d_in[0];
    const float* seeds = (const float*)d_in[1];
    const float* W     = (const float*)d_in[2];
    const float* b     = (const float*)d_in[3];
    float*       out   = (float*)d_out;

    cudaFuncSetAttribute(mma_kernel,
                         cudaFuncAttributeMaxDynamicSharedMemorySize, SMEM_SZ);
    prep_W_kernel<<<(JPAD * KPAD + 255) / 256, 256>>>(W);
    mma_kernel<<<NROWS / MT, THREADS, SMEM_SZ>>>(x, seeds, b, out);
}

// round 9
// speedup vs baseline: 4.3506x; 1.0010x over previous
#include <cuda_runtime.h>
#include <cuda_bf16.h>

// GenerateNodes via bf16-split mma.sync (HMMA) GEMM — compute_103-safe.
//   out[m, o*20+node] = sum_c mix[m,c] * W[node*3+o, c] + b[node*3+o]
//   mix = concat(x[m,0:3200], seeds[m,0:15]); fp32 split into bf16 hi+lo,
//   D = Ahi*Bhi + Ahi*Blo + Alo*Bhi accumulated in fp32 registers.
// R8: 256 CTAs x 256 thr; 8 warps = 4 m-bands x 2 n-halves; 2 CTAs/SM.

#define NROWS   16384
#define KX      3200
#define KS      15
#define KTOT    3215
#define KPAD    3264      // 51 * 64
#define JDIM    60
#define JPAD    64
#define MT      64        // rows per CTA
#define THREADS 256

#define A_BYTES (MT * 128)        // 8192: 64 rows x 64 bf16 (128 B, SW128)
#define B_BYTES (JPAD * 128)      // 8192
#define STG     (2 * A_BYTES + 2 * B_BYTES)   // 32768 per stage
#define OFF_AHI(s) ((s) * STG)
#define OFF_ALO(s) ((s) * STG + A_BYTES)
#define OFF_BHI(s) ((s) * STG + 2 * A_BYTES)
#define OFF_BLO(s) ((s) * STG + 2 * A_BYTES + B_BYTES)
#define SMEM_SZ    (2 * STG)      // 65536 bytes

__device__ __align__(16) __nv_bfloat16 g_Whi[JPAD * KPAD];
__device__ __align__(16) __nv_bfloat16 g_Wlo[JPAD * KPAD];

// ------------------------- helpers -------------------------
__device__ __forceinline__ unsigned s2u(const void* p) {
    unsigned a;
    asm("{ .reg .u64 t; cvta.to.shared.u64 t, %1; cvt.u32.u64 %0, t; }"
        : "=r"(a) : "l"(p));
    return a;
}
__device__ __forceinline__ unsigned swz(unsigned off) {
    return off ^ ((off >> 3) & 0x70);
}
__device__ __forceinline__ unsigned pack_hi(float a, float b) {
    unsigned short ra = __bfloat16_as_ushort(__float2bfloat16_rn(a));
    unsigned short rb = __bfloat16_as_ushort(__float2bfloat16_rn(b));
    return (unsigned)ra | ((unsigned)rb << 16);
}
__device__ __forceinline__ void ldsm4(unsigned addr, unsigned& r0, unsigned& r1,
                                      unsigned& r2, unsigned& r3) {
    asm volatile("ldmatrix.sync.aligned.m8n8.x4.shared.b16 {%0,%1,%2,%3}, [%4];"
                 : "=r"(r0), "=r"(r1), "=r"(r2), "=r"(r3) : "r"(addr));
}
__device__ __forceinline__ void mmabf16(float* c, unsigned a0, unsigned a1,
                                        unsigned a2, unsigned a3,
                                        unsigned b0, unsigned b1) {
    asm volatile(
        "mma.sync.aligned.m16n8k16.row.col.f32.bf16.bf16.f32 "
        "{%0,%1,%2,%3}, {%4,%5,%6,%7}, {%8,%9}, {%0,%1,%2,%3};"
        : "+f"(c[0]), "+f"(c[1]), "+f"(c[2]), "+f"(c[3])
        : "r"(a0), "r"(a1), "r"(a2), "r"(a3), "r"(b0), "r"(b1));
}
__device__ __forceinline__ void cpasync16(unsigned dst, const void* src) {
    asm volatile("cp.async.cg.shared.global [%0], [%1], 16;"
                 :: "r"(dst), "l"(src) : "memory");
}

// ------------------ kernel 1: split W into bf16 hi/lo ------------------
__global__ void prep_W_kernel(const float* __restrict__ W) {
    int idx = blockIdx.x * 256 + threadIdx.x;
    if (idx >= JPAD * KPAD) return;
    int j = idx / KPAD;
    int c = idx - j * KPAD;
    float v = (j < JDIM && c < KTOT) ? W[(size_t)j * KTOT + c] : 0.0f;
    __nv_bfloat16 hi = __float2bfloat16_rn(v);
    g_Whi[idx] = hi;
    g_Wlo[idx] = __float2bfloat16_rn(v - __bfloat162float(hi));
}

// ------------------------- main GEMM kernel -------------------------
__global__ __launch_bounds__(THREADS, 2)
void mma_kernel(const float* __restrict__ x, const float* __restrict__ seeds,
                const float* __restrict__ bias, float* __restrict__ out)
{
    extern __shared__ char smem[];
    const unsigned sb = s2u(smem);
    const int tid  = threadIdx.x;
    const int lane = tid & 31;
    const int warp = tid >> 5;            // 8 warps
    const int mb   = warp >> 1;           // m-band: rows 16mb..16mb+15
    const int nh   = warp & 1;            // n-half: cols 32nh..32nh+31
    const int row0 = blockIdx.x * MT;

    // ldmatrix lane geometry
    const int amat  = lane >> 3;
    const int arow  = 16 * mb + 8 * (amat & 1) + (lane & 7);
    const int acolb = (amat >> 1) * 16;              // byte offset within k16
    const int brow  = (lane & 7);
    const int bnt   = (lane >> 4) & 1;               // ntile within pair
    const int bkb   = ((lane >> 3) & 1) * 16;        // byte k-offset

    // gmem->smem mappings: x tile = 64 rows x 16 float4 = 1024 float4, 4 iters
    const int xr_r[4] = { (tid      ) >> 4, (tid + 256) >> 4,
                          (tid + 512) >> 4, (tid + 768) >> 4 };
    const int xq  = tid & 15;
    // W tile (per half) = 64 j x 8 chunks of 16B = 512; 2 iters of 256 thr
    const int wj[2] = { tid >> 3, (tid + 256) >> 3 };
    const int wqq = tid & 7;

    float acc[4][4];
    #pragma unroll
    for (int n = 0; n < 4; n++)
        #pragma unroll
        for (int q = 0; q < 4; q++) acc[n][q] = 0.0f;

    float4 xr[4];

    #define LOADX(ch) { _Pragma("unroll") \
        for (int i = 0; i < 4; i++) \
            xr[i] = *reinterpret_cast<const float4*>( \
                x + (size_t)(row0 + xr_r[i]) * KX + (ch) * 64 + 4 * xq); }
    #define CPW(ch, s) { _Pragma("unroll") \
        for (int i = 0; i < 2; i++) { \
            const unsigned so = swz((unsigned)(wj[i] * 128 + 16 * wqq)); \
            cpasync16(sb + OFF_BHI(s) + so, \
                      &g_Whi[(size_t)wj[i] * KPAD + (ch) * 64 + 8 * wqq]); \
            cpasync16(sb + OFF_BLO(s) + so, \
                      &g_Wlo[(size_t)wj[i] * KPAD + (ch) * 64 + 8 * wqq]); \
        } \
        asm volatile("cp.async.commit_group;" ::: "memory"); }
    #define STSX(s) { _Pragma("unroll") \
        for (int i = 0; i < 4; i++) { \
            const float4 v = xr[i]; \
            const unsigned off = swz((unsigned)(xr_r[i] * 128 + 8 * xq)); \
            float h0 = __bfloat162float(__float2bfloat16_rn(v.x)); \
            float h1 = __bfloat162float(__float2bfloat16_rn(v.y)); \
            float h2 = __bfloat162float(__float2bfloat16_rn(v.z)); \
            float h3 = __bfloat162float(__float2bfloat16_rn(v.w)); \
            *reinterpret_cast<unsigned*>(smem + OFF_AHI(s) + off)     = pack_hi(v.x, v.y); \
            *reinterpret_cast<unsigned*>(smem + OFF_AHI(s) + off + 4) = pack_hi(v.z, v.w); \
            *reinterpret_cast<unsigned*>(smem + OFF_ALO(s) + off)     = pack_hi(v.x - h0, v.y - h1); \
            *reinterpret_cast<unsigned*>(smem + OFF_ALO(s) + off + 4) = pack_hi(v.z - h2, v.w - h3); } }

    #define COMPUTE(s) { \
        const unsigned ahiB = sb + OFF_AHI(s), aloB = sb + OFF_ALO(s); \
        const unsigned bhiB = sb + OFF_BHI(s), bloB = sb + OFF_BLO(s); \
        _Pragma("unroll") \
        for (int kk = 0; kk < 4; kk++) { \
            const unsigned aoff = swz((unsigned)(arow * 128 + 32 * kk + acolb)); \
            unsigned ah0, ah1, ah2, ah3, al0, al1, al2, al3; \
            ldsm4(ahiB + aoff, ah0, ah1, ah2, ah3); \
            ldsm4(aloB + aoff, al0, al1, al2, al3); \
            _Pragma("unroll") \
            for (int ntp = 0; ntp < 2; ntp++) { \
                const unsigned boff = swz((unsigned)( \
                    (8 * (4 * nh + 2 * ntp + bnt) + brow) * 128 + 32 * kk + bkb)); \
                unsigned bh0, bh1, bh2, bh3, bl0, bl1, bl2, bl3; \
                ldsm4(bhiB + boff, bh0, bh1, bh2, bh3); \
                ldsm4(bloB + boff, bl0, bl1, bl2, bl3); \
                mmabf16(acc[2 * ntp],     ah0, ah1, ah2, ah3, bh0, bh1); \
                mmabf16(acc[2 * ntp],     ah0, ah1, ah2, ah3, bl0, bl1); \
                mmabf16(acc[2 * ntp],     al0, al1, al2, al3, bh0, bh1); \
                mmabf16(acc[2 * ntp + 1], ah0, ah1, ah2, ah3, bh2, bh3); \
                mmabf16(acc[2 * ntp + 1], ah0, ah1, ah2, ah3, bl2, bl3); \
                mmabf16(acc[2 * ntp + 1], al0, al1, al2, al3, bh2, bh3); \
            } \
        } }

    // ---------------- pipeline: 1 sync per chunk, ping-pong stages ----------------
    CPW(0, 0);
    LOADX(0);

    for (int ch = 0; ch < 50; ch++) {
        const int s = ch & 1;
        STSX(s);                                           // x(ch) -> stage s
        asm volatile("cp.async.wait_group 0;" ::: "memory");  // W(ch) arrived
        __syncthreads();                                   // stage s ready; s^1 free
        CPW(ch + 1, s ^ 1);                                // W(ch+1) async
        if (ch + 1 < 50) LOADX(ch + 1);                    // x(ch+1) -> regs
        COMPUTE(s);
    }

    // ---- seeds chunk (ch = 50, stage 0) ----
    for (int i = tid; i < (2 * A_BYTES) / 16; i += THREADS)
        *reinterpret_cast<uint4*>(smem + OFF_AHI(0) + 16 * i) = make_uint4(0, 0, 0, 0);
    __syncthreads();                                       // zeros visible
    for (int i = tid; i < MT * KS; i += THREADS) {
        const int r = i / KS, c = i - r * KS;
        const float v = seeds[(size_t)(row0 + r) * KS + c];
        const unsigned off = swz((unsigned)(r * 128 + 2 * c));
        __nv_bfloat16 hi = __float2bfloat16_rn(v);
        *reinterpret_cast<__nv_bfloat16*>(smem + OFF_AHI(0) + off) = hi;
        *reinterpret_cast<__nv_bfloat16*>(smem + OFF_ALO(0) + off) =
            __float2bfloat16_rn(v - __bfloat162float(hi));
    }
    asm volatile("cp.async.wait_group 0;" ::: "memory");   // W(50) arrived
    __syncthreads();
    COMPUTE(0);

    // ---- epilogue: frags -> smem -> permuted+bias store ----
    __syncthreads();                                       // all computes done
    float* red = reinterpret_cast<float*>(smem);           // [64][68]
    const int g = lane >> 2, t = lane & 3;
    #pragma unroll
    for (int nt = 0; nt < 4; nt++) {
        const int col = 32 * nh + 8 * nt + 2 * t;
        red[(16 * mb + g)     * 68 + col]     = acc[nt][0];
        red[(16 * mb + g)     * 68 + col + 1] = acc[nt][1];
        red[(16 * mb + 8 + g) * 68 + col]     = acc[nt][2];
        red[(16 * mb + 8 + g) * 68 + col + 1] = acc[nt][3];
    }
    __syncthreads();
    for (int i = tid; i < MT * JDIM; i += THREADS) {
        const int r = i / JDIM, pos = i - r * JDIM;
        const int o = pos / 20, node = pos - 20 * o;
        const int j = node * 3 + o;
        out[(size_t)row0 * JDIM + i] = red[r * 68 + j] + bias[j];
    }
}

extern "C" void kernel_launch(void* const* d_in, const int* in_sizes, int n_in,
                              void* d_out, int out_size)
{
    const float* x     = (const float*)d_in[0];
    const float* seeds = (const float*)d_in[1];
    const float* W     = (const float*)d_in[2];
    const float* b     = (const float*)d_in[3];
    float*       out   = (float*)d_out;

    cudaFuncSetAttribute(mma_kernel,
                         cudaFuncAttributeMaxDynamicSharedMemorySize, SMEM_SZ);
    prep_W_kernel<<<(JPAD * KPAD + 255) / 256, 256>>>(W);
    mma_kernel<<<NROWS / MT, THREADS, SMEM_SZ>>>(x, seeds, b, out);
}

// round 10
// speedup vs baseline: 6.1579x; 1.4154x over previous
#include <cuda_runtime.h>
#include <cuda_fp16.h>

// GenerateNodes via fp16 2-term split mma.sync (HMMA) GEMM — compute_103-safe.
//   out[m, o*20+node] = sum_c mix[m,c] * W[node*3+o, c] + b[node*3+o]
//   mix = concat(x[m,0:3200], seeds[m,0:15]);
//   A split: hi = fp16(a), lo = fp16(a - hi);  W: single fp16.
//   D = Ahi*Wh + Alo*Wh, fp32 accumulate. Dropped A*(W - Wh) ~ 1.4e-4 rel.
// R9: 256 CTAs x 256 thr; 8 warps = 4 m-bands x 2 n-halves; 2 CTAs/SM.

#define NROWS   16384
#define KX      3200
#define KS      15
#define KTOT    3215
#define KPAD    3264      // 51 * 64
#define JDIM    60
#define JPAD    64
#define MT      64        // rows per CTA
#define THREADS 256

#define A_BYTES (MT * 128)        // 8192: 64 rows x 64 fp16 (128 B, SW128)
#define B_BYTES (JPAD * 128)      // 8192
#define STG     (2 * A_BYTES + B_BYTES)   // 24576 per stage
#define OFF_AHI(s) ((s) * STG)
#define OFF_ALO(s) ((s) * STG + A_BYTES)
#define OFF_BHI(s) ((s) * STG + 2 * A_BYTES)
#define SMEM_SZ    (2 * STG)      // 49152 bytes

__device__ __align__(16) __half g_Wh[JPAD * KPAD];

// ------------------------- helpers -------------------------
__device__ __forceinline__ unsigned s2u(const void* p) {
    unsigned a;
    asm("{ .reg .u64 t; cvta.to.shared.u64 t, %1; cvt.u32.u64 %0, t; }"
        : "=r"(a) : "l"(p));
    return a;
}
__device__ __forceinline__ unsigned swz(unsigned off) {
    return off ^ ((off >> 3) & 0x70);
}
__device__ __forceinline__ unsigned pack_h(float a, float b) {
    unsigned short ra = __half_as_ushort(__float2half_rn(a));
    unsigned short rb = __half_as_ushort(__float2half_rn(b));
    return (unsigned)ra | ((unsigned)rb << 16);
}
__device__ __forceinline__ void ldsm4(unsigned addr, unsigned& r0, unsigned& r1,
                                      unsigned& r2, unsigned& r3) {
    asm volatile("ldmatrix.sync.aligned.m8n8.x4.shared.b16 {%0,%1,%2,%3}, [%4];"
                 : "=r"(r0), "=r"(r1), "=r"(r2), "=r"(r3) : "r"(addr));
}
__device__ __forceinline__ void mmaf16(float* c, unsigned a0, unsigned a1,
                                       unsigned a2, unsigned a3,
                                       unsigned b0, unsigned b1) {
    asm volatile(
        "mma.sync.aligned.m16n8k16.row.col.f32.f16.f16.f32 "
        "{%0,%1,%2,%3}, {%4,%5,%6,%7}, {%8,%9}, {%0,%1,%2,%3};"
        : "+f"(c[0]), "+f"(c[1]), "+f"(c[2]), "+f"(c[3])
        : "r"(a0), "r"(a1), "r"(a2), "r"(a3), "r"(b0), "r"(b1));
}
__device__ __forceinline__ void cpasync16(unsigned dst, const void* src) {
    asm volatile("cp.async.cg.shared.global [%0], [%1], 16;"
                 :: "r"(dst), "l"(src) : "memory");
}

// ------------------ kernel 1: W -> fp16 ------------------
__global__ void prep_W_kernel(const float* __restrict__ W) {
    int idx = blockIdx.x * 256 + threadIdx.x;
    if (idx >= JPAD * KPAD) return;
    int j = idx / KPAD;
    int c = idx - j * KPAD;
    float v = (j < JDIM && c < KTOT) ? W[(size_t)j * KTOT + c] : 0.0f;
    g_Wh[idx] = __float2half_rn(v);
}

// ------------------------- main GEMM kernel -------------------------
__global__ __launch_bounds__(THREADS, 2)
void mma_kernel(const float* __restrict__ x, const float* __restrict__ seeds,
                const float* __restrict__ bias, float* __restrict__ out)
{
    extern __shared__ char smem[];
    const unsigned sb = s2u(smem);
    const int tid  = threadIdx.x;
    const int lane = tid & 31;
    const int warp = tid >> 5;            // 8 warps
    const int mb   = warp >> 1;           // m-band: rows 16mb..16mb+15
    const int nh   = warp & 1;            // n-half: cols 32nh..32nh+31
    const int row0 = blockIdx.x * MT;

    // ldmatrix lane geometry
    const int amat  = lane >> 3;
    const int arow  = 16 * mb + 8 * (amat & 1) + (lane & 7);
    const int acolb = (amat >> 1) * 16;              // byte offset within k16
    const int brow  = (lane & 7);
    const int bnt   = (lane >> 4) & 1;               // ntile within pair
    const int bkb   = ((lane >> 3) & 1) * 16;        // byte k-offset

    // gmem->smem mappings: x tile = 64 rows x 16 float4 = 1024 float4, 4 iters
    const int xr_r[4] = { (tid      ) >> 4, (tid + 256) >> 4,
                          (tid + 512) >> 4, (tid + 768) >> 4 };
    const int xq  = tid & 15;
    // W tile = 64 j x 8 chunks of 16B = 512 transfers; 2 iters of 256 thr
    const int wj[2] = { tid >> 3, (tid + 256) >> 3 };
    const int wqq = tid & 7;

    float acc[4][4];
    #pragma unroll
    for (int n = 0; n < 4; n++)
        #pragma unroll
        for (int q = 0; q < 4; q++) acc[n][q] = 0.0f;

    float4 xr[4];

    #define LOADX(ch) { _Pragma("unroll") \
        for (int i = 0; i < 4; i++) \
            xr[i] = *reinterpret_cast<const float4*>( \
                x + (size_t)(row0 + xr_r[i]) * KX + (ch) * 64 + 4 * xq); }
    #define CPW(ch, s) { _Pragma("unroll") \
        for (int i = 0; i < 2; i++) { \
            const unsigned so = swz((unsigned)(wj[i] * 128 + 16 * wqq)); \
            cpasync16(sb + OFF_BHI(s) + so, \
                      &g_Wh[(size_t)wj[i] * KPAD + (ch) * 64 + 8 * wqq]); \
        } \
        asm volatile("cp.async.commit_group;" ::: "memory"); }
    #define STSX(s) { _Pragma("unroll") \
        for (int i = 0; i < 4; i++) { \
            const float4 v = xr[i]; \
            const unsigned off = swz((unsigned)(xr_r[i] * 128 + 8 * xq)); \
            float h0 = __half2float(__float2half_rn(v.x)); \
            float h1 = __half2float(__float2half_rn(v.y)); \
            float h2 = __half2float(__float2half_rn(v.z)); \
            float h3 = __half2float(__float2half_rn(v.w)); \
            *reinterpret_cast<unsigned*>(smem + OFF_AHI(s) + off)     = pack_h(v.x, v.y); \
            *reinterpret_cast<unsigned*>(smem + OFF_AHI(s) + off + 4) = pack_h(v.z, v.w); \
            *reinterpret_cast<unsigned*>(smem + OFF_ALO(s) + off)     = pack_h(v.x - h0, v.y - h1); \
            *reinterpret_cast<unsigned*>(smem + OFF_ALO(s) + off + 4) = pack_h(v.z - h2, v.w - h3); } }

    #define COMPUTE(s) { \
        const unsigned ahiB = sb + OFF_AHI(s), aloB = sb + OFF_ALO(s); \
        const unsigned bhiB = sb + OFF_BHI(s); \
        _Pragma("unroll") \
        for (int kk = 0; kk < 4; kk++) { \
            const unsigned aoff = swz((unsigned)(arow * 128 + 32 * kk + acolb)); \
            unsigned ah0, ah1, ah2, ah3, al0, al1, al2, al3; \
            ldsm4(ahiB + aoff, ah0, ah1, ah2, ah3); \
            ldsm4(aloB + aoff, al0, al1, al2, al3); \
            _Pragma("unroll") \
            for (int ntp = 0; ntp < 2; ntp++) { \
                const unsigned boff = swz((unsigned)( \
                    (8 * (4 * nh + 2 * ntp + bnt) + brow) * 128 + 32 * kk + bkb)); \
                unsigned bh0, bh1, bh2, bh3; \
                ldsm4(bhiB + boff, bh0, bh1, bh2, bh3); \
                mmaf16(acc[2 * ntp],     ah0, ah1, ah2, ah3, bh0, bh1); \
                mmaf16(acc[2 * ntp],     al0, al1, al2, al3, bh0, bh1); \
                mmaf16(acc[2 * ntp + 1], ah0, ah1, ah2, ah3, bh2, bh3); \
                mmaf16(acc[2 * ntp + 1], al0, al1, al2, al3, bh2, bh3); \
            } \
        } }

    // ---------------- pipeline: 1 sync per chunk, ping-pong stages ----------------
    CPW(0, 0);
    LOADX(0);

    for (int ch = 0; ch < 50; ch++) {
        const int s = ch & 1;
        STSX(s);                                           // x(ch) -> stage s
        asm volatile("cp.async.wait_group 0;" ::: "memory");  // W(ch) arrived
        __syncthreads();                                   // stage s ready; s^1 free
        CPW(ch + 1, s ^ 1);                                // W(ch+1) async
        if (ch + 1 < 50) LOADX(ch + 1);                    // x(ch+1) -> regs
        COMPUTE(s);
    }

    // ---- seeds chunk (ch = 50, stage 0) ----
    for (int i = tid; i < (2 * A_BYTES) / 16; i += THREADS)
        *reinterpret_cast<uint4*>(smem + OFF_AHI(0) + 16 * i) = make_uint4(0, 0, 0, 0);
    __syncthreads();                                       // zeros visible
    for (int i = tid; i < MT * KS; i += THREADS) {
        const int r = i / KS, c = i - r * KS;
        const float v = seeds[(size_t)(row0 + r) * KS + c];
        const unsigned off = swz((unsigned)(r * 128 + 2 * c));
        __half hi = __float2half_rn(v);
        *reinterpret_cast<__half*>(smem + OFF_AHI(0) + off) = hi;
        *reinterpret_cast<__half*>(smem + OFF_ALO(0) + off) =
            __float2half_rn(v - __half2float(hi));
    }
    asm volatile("cp.async.wait_group 0;" ::: "memory");   // W(50) arrived
    __syncthreads();
    COMPUTE(0);

    // ---- epilogue: frags -> smem -> permuted+bias store ----
    __syncthreads();                                       // all computes done
    float* red = reinterpret_cast<float*>(smem);           // [64][68]
    const int g = lane >> 2, t = lane & 3;
    #pragma unroll
    for (int nt = 0; nt < 4; nt++) {
        const int col = 32 * nh + 8 * nt + 2 * t;
        red[(16 * mb + g)     * 68 + col]     = acc[nt][0];
        red[(16 * mb + g)     * 68 + col + 1] = acc[nt][1];
        red[(16 * mb + 8 + g) * 68 + col]     = acc[nt][2];
        red[(16 * mb + 8 + g) * 68 + col + 1] = acc[nt][3];
    }
    __syncthreads();
    for (int i = tid; i < MT * JDIM; i += THREADS) {
        const int r = i / JDIM, pos = i - r * JDIM;
        const int o = pos / 20, node = pos - 20 * o;
        const int j = node * 3 + o;
        out[(size_t)row0 * JDIM + i] = red[r * 68 + j] + bias[j];
    }
}

extern "C" void kernel_launch(void* const* d_in, const int* in_sizes, int n_in,
                              void* d_out, int out_size)
{
    const float* x     = (const float*)d_in[0];
    const float* seeds = (const float*)d_in[1];
    const float* W     = (const float*)d_in[2];
    const float* b     = (const float*)d_in[3];
    float*       out   = (float*)d_out;

    cudaFuncSetAttribute(mma_kernel,
                         cudaFuncAttributeMaxDynamicSharedMemorySize, SMEM_SZ);
    prep_W_kernel<<<(JPAD * KPAD + 255) / 256, 256>>>(W);
    mma_kernel<<<NROWS / MT, THREADS, SMEM_SZ>>>(x, seeds, b, out);
}

// round 11
// speedup vs baseline: 6.5949x; 1.0710x over previous
#include <cuda_runtime.h>
#include <cuda_fp16.h>

// GenerateNodes via pure-fp16 mma.sync (HMMA) GEMM — compute_103-safe.
//   out[m, o*20+node] = sum_c mix[m,c] * W[node*3+o, c] + b[node*3+o]
//   mix = concat(x[m,0:3200], seeds[m,0:15]);
//   A = fp16(mix), W = fp16(W), fp32 accumulate. rel_err ~3e-4 (<1e-3).
// R10: 256 CTAs x 256 thr; 8 warps = 4 m-bands x 2 n-halves.

#define NROWS   16384
#define KX      3200
#define KS      15
#define KTOT    3215
#define KPAD    3264      // 51 * 64
#define JDIM    60
#define JPAD    64
#define MT      64        // rows per CTA
#define THREADS 256

#define A_BYTES (MT * 128)        // 8192: 64 rows x 64 fp16 (128 B, SW128)
#define B_BYTES (JPAD * 128)      // 8192
#define STG     (A_BYTES + B_BYTES)       // 16384 per stage
#define OFF_A(s)  ((s) * STG)
#define OFF_B(s)  ((s) * STG + A_BYTES)
#define SMEM_SZ   (2 * STG)       // 32768 bytes

__device__ __align__(16) __half g_Wh[JPAD * KPAD];

// ------------------------- helpers -------------------------
__device__ __forceinline__ unsigned s2u(const void* p) {
    unsigned a;
    asm("{ .reg .u64 t; cvta.to.shared.u64 t, %1; cvt.u32.u64 %0, t; }"
        : "=r"(a) : "l"(p));
    return a;
}
__device__ __forceinline__ unsigned swz(unsigned off) {
    return off ^ ((off >> 3) & 0x70);
}
__device__ __forceinline__ unsigned pack_h(float a, float b) {
    unsigned short ra = __half_as_ushort(__float2half_rn(a));
    unsigned short rb = __half_as_ushort(__float2half_rn(b));
    return (unsigned)ra | ((unsigned)rb << 16);
}
__device__ __forceinline__ void ldsm4(unsigned addr, unsigned& r0, unsigned& r1,
                                      unsigned& r2, unsigned& r3) {
    asm volatile("ldmatrix.sync.aligned.m8n8.x4.shared.b16 {%0,%1,%2,%3}, [%4];"
                 : "=r"(r0), "=r"(r1), "=r"(r2), "=r"(r3) : "r"(addr));
}
__device__ __forceinline__ void mmaf16(float* c, unsigned a0, unsigned a1,
                                       unsigned a2, unsigned a3,
                                       unsigned b0, unsigned b1) {
    asm volatile(
        "mma.sync.aligned.m16n8k16.row.col.f32.f16.f16.f32 "
        "{%0,%1,%2,%3}, {%4,%5,%6,%7}, {%8,%9}, {%0,%1,%2,%3};"
        : "+f"(c[0]), "+f"(c[1]), "+f"(c[2]), "+f"(c[3])
        : "r"(a0), "r"(a1), "r"(a2), "r"(a3), "r"(b0), "r"(b1));
}
__device__ __forceinline__ void cpasync16(unsigned dst, const void* src) {
    asm volatile("cp.async.cg.shared.global [%0], [%1], 16;"
                 :: "r"(dst), "l"(src) : "memory");
}

// ------------------ kernel 1: W -> fp16 ------------------
__global__ void prep_W_kernel(const float* __restrict__ W) {
    int idx = blockIdx.x * 256 + threadIdx.x;
    if (idx >= JPAD * KPAD) return;
    int j = idx / KPAD;
    int c = idx - j * KPAD;
    float v = (j < JDIM && c < KTOT) ? W[(size_t)j * KTOT + c] : 0.0f;
    g_Wh[idx] = __float2half_rn(v);
}

// ------------------------- main GEMM kernel -------------------------
__global__ __launch_bounds__(THREADS, 2)
void mma_kernel(const float* __restrict__ x, const float* __restrict__ seeds,
                const float* __restrict__ bias, float* __restrict__ out)
{
    extern __shared__ char smem[];
    const unsigned sb = s2u(smem);
    const int tid  = threadIdx.x;
    const int lane = tid & 31;
    const int warp = tid >> 5;            // 8 warps
    const int mb   = warp >> 1;           // m-band: rows 16mb..16mb+15
    const int nh   = warp & 1;            // n-half: cols 32nh..32nh+31
    const int row0 = blockIdx.x * MT;

    // ldmatrix lane geometry
    const int amat  = lane >> 3;
    const int arow  = 16 * mb + 8 * (amat & 1) + (lane & 7);
    const int acolb = (amat >> 1) * 16;              // byte offset within k16
    const int brow  = (lane & 7);
    const int bnt   = (lane >> 4) & 1;               // ntile within pair
    const int bkb   = ((lane >> 3) & 1) * 16;        // byte k-offset

    // gmem->smem mappings: x tile = 64 rows x 16 float4 = 1024 float4, 4 iters
    const int xr_r[4] = { (tid      ) >> 4, (tid + 256) >> 4,
                          (tid + 512) >> 4, (tid + 768) >> 4 };
    const int xq  = tid & 15;
    // W tile = 64 j x 8 chunks of 16B = 512 transfers; 2 iters of 256 thr
    const int wj[2] = { tid >> 3, (tid + 256) >> 3 };
    const int wqq = tid & 7;

    float acc[4][4];
    #pragma unroll
    for (int n = 0; n < 4; n++)
        #pragma unroll
        for (int q = 0; q < 4; q++) acc[n][q] = 0.0f;

    float4 xr[4];

    #define LOADX(ch) { _Pragma("unroll") \
        for (int i = 0; i < 4; i++) \
            xr[i] = *reinterpret_cast<const float4*>( \
                x + (size_t)(row0 + xr_r[i]) * KX + (ch) * 64 + 4 * xq); }
    #define CPW(ch, s) { _Pragma("unroll") \
        for (int i = 0; i < 2; i++) { \
            const unsigned so = swz((unsigned)(wj[i] * 128 + 16 * wqq)); \
            cpasync16(sb + OFF_B(s) + so, \
                      &g_Wh[(size_t)wj[i] * KPAD + (ch) * 64 + 8 * wqq]); \
        } \
        asm volatile("cp.async.commit_group;" ::: "memory"); }
    #define STSX(s) { _Pragma("unroll") \
        for (int i = 0; i < 4; i++) { \
            const float4 v = xr[i]; \
            const unsigned off = swz((unsigned)(xr_r[i] * 128 + 8 * xq)); \
            *reinterpret_cast<unsigned*>(smem + OFF_A(s) + off)     = pack_h(v.x, v.y); \
            *reinterpret_cast<unsigned*>(smem + OFF_A(s) + off + 4) = pack_h(v.z, v.w); } }

    #define COMPUTE(s) { \
        const unsigned aB = sb + OFF_A(s); \
        const unsigned bB = sb + OFF_B(s); \
        _Pragma("unroll") \
        for (int kk = 0; kk < 4; kk++) { \
            const unsigned aoff = swz((unsigned)(arow * 128 + 32 * kk + acolb)); \
            unsigned a0, a1, a2, a3; \
            ldsm4(aB + aoff, a0, a1, a2, a3); \
            _Pragma("unroll") \
            for (int ntp = 0; ntp < 2; ntp++) { \
                const unsigned boff = swz((unsigned)( \
                    (8 * (4 * nh + 2 * ntp + bnt) + brow) * 128 + 32 * kk + bkb)); \
                unsigned b0, b1, b2, b3; \
                ldsm4(bB + boff, b0, b1, b2, b3); \
                mmaf16(acc[2 * ntp],     a0, a1, a2, a3, b0, b1); \
                mmaf16(acc[2 * ntp + 1], a0, a1, a2, a3, b2, b3); \
            } \
        } }

    // ---------------- pipeline: 1 sync per chunk, ping-pong stages ----------------
    CPW(0, 0);
    LOADX(0);

    for (int ch = 0; ch < 50; ch++) {
        const int s = ch & 1;
        STSX(s);                                           // x(ch) -> stage s
        asm volatile("cp.async.wait_group 0;" ::: "memory");  // W(ch) arrived
        __syncthreads();                                   // stage s ready; s^1 free
        CPW(ch + 1, s ^ 1);                                // W(ch+1) async
        if (ch + 1 < 50) LOADX(ch + 1);                    // x(ch+1) -> regs
        COMPUTE(s);
    }

    // ---- seeds chunk (ch = 50, stage 0) ----
    for (int i = tid; i < A_BYTES / 16; i += THREADS)
        *reinterpret_cast<uint4*>(smem + OFF_A(0) + 16 * i) = make_uint4(0, 0, 0, 0);
    __syncthreads();                                       // zeros visible
    for (int i = tid; i < MT * KS; i += THREADS) {
        const int r = i / KS, c = i - r * KS;
        const float v = seeds[(size_t)(row0 + r) * KS + c];
        const unsigned off = swz((unsigned)(r * 128 + 2 * c));
        *reinterpret_cast<__half*>(smem + OFF_A(0) + off) = __float2half_rn(v);
    }
    asm volatile("cp.async.wait_group 0;" ::: "memory");   // W(50) arrived
    __syncthreads();
    COMPUTE(0);

    // ---- epilogue: frags -> smem -> permuted+bias store ----
    __syncthreads();                                       // all computes done
    float* red = reinterpret_cast<float*>(smem);           // [64][68]
    const int g = lane >> 2, t = lane & 3;
    #pragma unroll
    for (int nt = 0; nt < 4; nt++) {
        const int col = 32 * nh + 8 * nt + 2 * t;
        red[(16 * mb + g)     * 68 + col]     = acc[nt][0];
        red[(16 * mb + g)     * 68 + col + 1] = acc[nt][1];
        red[(16 * mb + 8 + g) * 68 + col]     = acc[nt][2];
        red[(16 * mb + 8 + g) * 68 + col + 1] = acc[nt][3];
    }
    __syncthreads();
    for (int i = tid; i < MT * JDIM; i += THREADS) {
        const int r = i / JDIM, pos = i - r * JDIM;
        const int o = pos / 20, node = pos - 20 * o;
        const int j = node * 3 + o;
        out[(size_t)row0 * JDIM + i] = red[r * 68 + j] + bias[j];
    }
}

extern "C" void kernel_launch(void* const* d_in, const int* in_sizes, int n_in,
                              void* d_out, int out_size)
{
    const float* x     = (const float*)d_in[0];
    const float* seeds = (const float*)d_in[1];
    const float* W     = (const float*)d_in[2];
    const float* b     = (const float*)d_in[3];
    float*       out   = (float*)d_out;

    cudaFuncSetAttribute(mma_kernel,
                         cudaFuncAttributeMaxDynamicSharedMemorySize, SMEM_SZ);
    prep_W_kernel<<<(JPAD * KPAD + 255) / 256, 256>>>(W);
    mma_kernel<<<NROWS / MT, THREADS, SMEM_SZ>>>(x, seeds, b, out);
}

// round 13
// speedup vs baseline: 7.7676x; 1.1778x over previous
#include <cuda_runtime.h>
#include <cuda_fp16.h>

// GenerateNodes via pure-fp16 mma.sync (HMMA) GEMM — compute_103-safe.
//   out[m, o*20+node] = sum_c mix[m,c] * W[node*3+o, c] + b[node*3+o]
//   mix = concat(x[m,0:3200], seeds[m,0:15]);
//   A = fp16(mix), W = fp16(W), fp32 accumulate. rel_err ~3e-4 (<1e-3).
// R11: KC=128 chunks (26 syncs vs 51), 8-deep x reg prefetch, 2 CTAs/SM.

#define NROWS   16384
#define KX      3200
#define KS      15
#define KTOT    3215
#define KPAD    3328      // 26 * 128
#define NCH     25        // full x chunks of 128; chunk 25 = seeds
#define JDIM    60
#define JPAD    64
#define MT      64        // rows per CTA
#define THREADS 256

#define SUB     8192              // one 64-row x 64-col fp16 SW128 sub-tile
#define A_BYTES (2 * SUB)         // 16384: 64 rows x 128 fp16 (2 k-blocks)
#define B_BYTES (2 * SUB)         // 16384
#define STG     (A_BYTES + B_BYTES)       // 32768 per stage
#define OFF_A(s)  ((s) * STG)
#define OFF_B(s)  ((s) * STG + A_BYTES)
#define SMEM_SZ   (2 * STG)       // 65536 bytes

__device__ __align__(16) __half g_Wh[JPAD * KPAD];

// ------------------------- helpers -------------------------
__device__ __forceinline__ unsigned s2u(const void* p) {
    unsigned a;
    asm("{ .reg .u64 t; cvta.to.shared.u64 t, %1; cvt.u32.u64 %0, t; }"
        : "=r"(a) : "l"(p));
    return a;
}
__device__ __forceinline__ unsigned swz(unsigned off) {
    return off ^ ((off >> 3) & 0x70);
}
__device__ __forceinline__ unsigned pack_h(float a, float b) {
    unsigned short ra = __half_as_ushort(__float2half_rn(a));
    unsigned short rb = __half_as_ushort(__float2half_rn(b));
    return (unsigned)ra | ((unsigned)rb << 16);
}
__device__ __forceinline__ void ldsm4(unsigned addr, unsigned& r0, unsigned& r1,
                                      unsigned& r2, unsigned& r3) {
    asm volatile("ldmatrix.sync.aligned.m8n8.x4.shared.b16 {%0,%1,%2,%3}, [%4];"
                 : "=r"(r0), "=r"(r1), "=r"(r2), "=r"(r3) : "r"(addr));
}
__device__ __forceinline__ void mmaf16(float* c, unsigned a0, unsigned a1,
                                       unsigned a2, unsigned a3,
                                       unsigned b0, unsigned b1) {
    asm volatile(
        "mma.sync.aligned.m16n8k16.row.col.f32.f16.f16.f32 "
        "{%0,%1,%2,%3}, {%4,%5,%6,%7}, {%8,%9}, {%0,%1,%2,%3};"
        : "+f"(c[0]), "+f"(c[1]), "+f"(c[2]), "+f"(c[3])
        : "r"(a0), "r"(a1), "r"(a2), "r"(a3), "r"(b0), "r"(b1));
}
__device__ __forceinline__ void cpasync16(unsigned dst, const void* src) {
    asm volatile("cp.async.cg.shared.global [%0], [%1], 16;"
                 :: "r"(dst), "l"(src) : "memory");
}

// ------------------ kernel 1: W -> fp16 ------------------
__global__ void prep_W_kernel(const float* __restrict__ W) {
    int idx = blockIdx.x * 256 + threadIdx.x;
    if (idx >= JPAD * KPAD) return;
    int j = idx / KPAD;
    int c = idx - j * KPAD;
    float v = (j < JDIM && c < KTOT) ? W[(size_t)j * KTOT + c] : 0.0f;
    g_Wh[idx] = __float2half_rn(v);
}

// ------------------------- main GEMM kernel -------------------------
__global__ __launch_bounds__(THREADS, 2)
void mma_kernel(const float* __restrict__ x, const float* __restrict__ seeds,
                const float* __restrict__ bias, float* __restrict__ out)
{
    extern __shared__ char smem[];
    const unsigned sb = s2u(smem);
    const int tid  = threadIdx.x;
    const int lane = tid & 31;
    const int warp = tid >> 5;            // 8 warps
    const int mb   = warp >> 1;           // m-band: rows 16mb..16mb+15
    const int nh   = warp & 1;            // n-half: cols 32nh..32nh+31
    const int row0 = blockIdx.x * MT;

    // ldmatrix lane geometry
    const int amat  = lane >> 3;
    const int arow  = 16 * mb + 8 * (amat & 1) + (lane & 7);
    const int acolb = (amat >> 1) * 16;              // byte offset within k16
    const int brow  = (lane & 7);
    const int bnt   = (lane >> 4) & 1;               // ntile within pair
    const int bkb   = ((lane >> 3) & 1) * 16;        // byte k-offset

    // x tile = 64 rows x 32 float4; warp reads 512B contiguous per row.
    const int xrw = tid >> 5;             // base row (0..7); row_i = xrw + 8i
    const int xq  = tid & 31;             // float4-col 0..31
    const int xkb = xq >> 4;              // k-block of this thread's column
    const int xq64 = xq & 15;
    // W tile per k-block = 64 j x 4 slots of 16B x 2 kb
    const int wj[2] = { tid >> 3, (tid + 256) >> 3 };
    const int wqq = tid & 7;

    float acc[4][4];
    #pragma unroll
    for (int n = 0; n < 4; n++)
        #pragma unroll
        for (int q = 0; q < 4; q++) acc[n][q] = 0.0f;

    float4 xr[8];

    #define LOADX(ch) { _Pragma("unroll") \
        for (int i = 0; i < 8; i++) \
            xr[i] = *reinterpret_cast<const float4*>( \
                x + (size_t)(row0 + xrw + 8 * i) * KX + (ch) * 128 + 4 * xq); }
    #define CPW(ch, s) { _Pragma("unroll") \
        for (int kb = 0; kb < 2; kb++) { \
            _Pragma("unroll") \
            for (int i = 0; i < 2; i++) { \
                const unsigned so = (unsigned)(kb * SUB) + swz((unsigned)(wj[i] * 128 + 16 * wqq)); \
                cpasync16(sb + OFF_B(s) + so, \
                          &g_Wh[(size_t)wj[i] * KPAD + (ch) * 128 + kb * 64 + 8 * wqq]); \
            } \
        } \
        asm volatile("cp.async.commit_group;" ::: "memory"); }
    #define STSX(s) { _Pragma("unroll") \
        for (int i = 0; i < 8; i++) { \
            const float4 v = xr[i]; \
            const unsigned off = (unsigned)(xkb * SUB) + \
                swz((unsigned)((xrw + 8 * i) * 128 + 8 * xq64)); \
            *reinterpret_cast<unsigned*>(smem + OFF_A(s) + off)     = pack_h(v.x, v.y); \
            *reinterpret_cast<unsigned*>(smem + OFF_A(s) + off + 4) = pack_h(v.z, v.w); } }

    #define COMPUTE(s) { \
        const unsigned aB = sb + OFF_A(s); \
        const unsigned bB = sb + OFF_B(s); \
        _Pragma("unroll") \
        for (int kk = 0; kk < 8; kk++) { \
            const int kb = kk >> 2, kl = kk & 3; \
            const unsigned aoff = (unsigned)(kb * SUB) + \
                swz((unsigned)(arow * 128 + 32 * kl + acolb)); \
            unsigned a0, a1, a2, a3; \
            ldsm4(aB + aoff, a0, a1, a2, a3); \
            _Pragma("unroll") \
            for (int ntp = 0; ntp < 2; ntp++) { \
                const unsigned boff = (unsigned)(kb * SUB) + swz((unsigned)( \
                    (8 * (4 * nh + 2 * ntp + bnt) + brow) * 128 + 32 * kl + bkb)); \
                unsigned b0, b1, b2, b3; \
                ldsm4(bB + boff, b0, b1, b2, b3); \
                mmaf16(acc[2 * ntp],     a0, a1, a2, a3, b0, b1); \
                mmaf16(acc[2 * ntp + 1], a0, a1, a2, a3, b2, b3); \
            } \
        } }

    // ---------------- pipeline: 1 sync per chunk, ping-pong stages ----------------
    CPW(0, 0);
    LOADX(0);

    for (int ch = 0; ch < NCH; ch++) {
        const int s = ch & 1;
        STSX(s);                                           // x(ch) -> stage s
        asm volatile("cp.async.wait_group 0;" ::: "memory");  // W(ch) arrived
        __syncthreads();                                   // stage s ready; s^1 free
        CPW(ch + 1, s ^ 1);                                // W(ch+1) async
        if (ch + 1 < NCH) LOADX(ch + 1);                   // x(ch+1) -> regs
        COMPUTE(s);
    }

    // ---- seeds chunk (ch = 25 -> stage 1; loop's last CPW targeted stage 1) ----
    for (int i = tid; i < A_BYTES / 16; i += THREADS)
        *reinterpret_cast<uint4*>(smem + OFF_A(1) + 16 * i) = make_uint4(0, 0, 0, 0);
    __syncthreads();                                       // zeros visible
    for (int i = tid; i < MT * KS; i += THREADS) {
        const int r = i / KS, c = i - r * KS;
        const float v = seeds[(size_t)(row0 + r) * KS + c];
        const unsigned off = swz((unsigned)(r * 128 + 2 * c));   // kb 0 (c < 64)
        *reinterpret_cast<__half*>(smem + OFF_A(1) + off) = __float2half_rn(v);
    }
    asm volatile("cp.async.wait_group 0;" ::: "memory");   // W(seeds) arrived
    __syncthreads();
    COMPUTE(1);

    // ---- epilogue: frags -> smem -> permuted+bias store ----
    __syncthreads();                                       // all computes done
    float* red = reinterpret_cast<float*>(smem);           // [64][68]
    const int g = lane >> 2, t = lane & 3;
    #pragma unroll
    for (int nt = 0; nt < 4; nt++) {
        const int col = 32 * nh + 8 * nt + 2 * t;
        red[(16 * mb + g)     * 68 + col]     = acc[nt][0];
        red[(16 * mb + g)     * 68 + col + 1] = acc[nt][1];
        red[(16 * mb + 8 + g) * 68 + col]     = acc[nt][2];
        red[(16 * mb + 8 + g) * 68 + col + 1] = acc[nt][3];
    }
    __syncthreads();
    for (int i = tid; i < MT * JDIM; i += THREADS) {
        const int r = i / JDIM, pos = i - r * JDIM;
        const int o = pos / 20, node = pos - 20 * o;
        const int j = node * 3 + o;
        out[(size_t)row0 * JDIM + i] = red[r * 68 + j] + bias[j];
    }
}

extern "C" void kernel_launch(void* const* d_in, const int* in_sizes, int n_in,
                              void* d_out, int out_size)
{
    const float* x     = (const float*)d_in[0];
    const float* seeds = (const float*)d_in[1];
    const float* W     = (const float*)d_in[2];
    const float* b     = (const float*)d_in[3];
    float*       out   = (float*)d_out;

    cudaFuncSetAttribute(mma_kernel,
                         cudaFuncAttributeMaxDynamicSharedMemorySize, SMEM_SZ);
    prep_W_kernel<<<(JPAD * KPAD + 255) / 256, 256>>>(W);
    mma_kernel<<<NROWS / MT, THREADS, SMEM_SZ>>>(x, seeds, b, out);
}

// round 14
// speedup vs baseline: 7.8655x; 1.0126x over previous
#include <cuda_runtime.h>
#include <cuda_fp16.h>

// GenerateNodes via pure-fp16 mma.sync (HMMA) GEMM — compute_103-safe.
//   out[m, o*20+node] = sum_c mix[m,c] * W[node*3+o, c] + b[node*3+o]
//   mix = concat(x[m,0:3200], seeds[m,0:15]);
//   A = fp16(mix), W = fp16(W), fp32 accumulate. rel_err ~3e-4 (<1e-3).
// R13: MT=32, 128 thr, 4 CTAs/SM (4 independent barrier domains), KC=128.

#define NROWS   16384
#define KX      3200
#define KS      15
#define KTOT    3215
#define KPAD    3328      // 26 * 128
#define NCH     25        // full x chunks of 128; chunk 25 = seeds
#define JDIM    60
#define JPAD    64
#define MT      32        // rows per CTA
#define THREADS 128

#define A_SUB   4096              // 32 rows x 64 fp16 (128 B, SW128)
#define B_SUB   8192              // 64 j x 64 fp16
#define A_BYTES (2 * A_SUB)       // 8192  (2 k-blocks)
#define B_BYTES (2 * B_SUB)       // 16384
#define STG     (A_BYTES + B_BYTES)       // 24576 per stage
#define OFF_A(s)  ((s) * STG)
#define OFF_B(s)  ((s) * STG + A_BYTES)
#define SMEM_SZ   (2 * STG)       // 49152 bytes

__device__ __align__(16) __half g_Wh[JPAD * KPAD];

// ------------------------- helpers -------------------------
__device__ __forceinline__ unsigned s2u(const void* p) {
    unsigned a;
    asm("{ .reg .u64 t; cvta.to.shared.u64 t, %1; cvt.u32.u64 %0, t; }"
        : "=r"(a) : "l"(p));
    return a;
}
__device__ __forceinline__ unsigned swz(unsigned off) {
    return off ^ ((off >> 3) & 0x70);
}
__device__ __forceinline__ unsigned pack_h(float a, float b) {
    unsigned short ra = __half_as_ushort(__float2half_rn(a));
    unsigned short rb = __half_as_ushort(__float2half_rn(b));
    return (unsigned)ra | ((unsigned)rb << 16);
}
__device__ __forceinline__ void ldsm4(unsigned addr, unsigned& r0, unsigned& r1,
                                      unsigned& r2, unsigned& r3) {
    asm volatile("ldmatrix.sync.aligned.m8n8.x4.shared.b16 {%0,%1,%2,%3}, [%4];"
                 : "=r"(r0), "=r"(r1), "=r"(r2), "=r"(r3) : "r"(addr));
}
__device__ __forceinline__ void mmaf16(float* c, unsigned a0, unsigned a1,
                                       unsigned a2, unsigned a3,
                                       unsigned b0, unsigned b1) {
    asm volatile(
        "mma.sync.aligned.m16n8k16.row.col.f32.f16.f16.f32 "
        "{%0,%1,%2,%3}, {%4,%5,%6,%7}, {%8,%9}, {%0,%1,%2,%3};"
        : "+f"(c[0]), "+f"(c[1]), "+f"(c[2]), "+f"(c[3])
        : "r"(a0), "r"(a1), "r"(a2), "r"(a3), "r"(b0), "r"(b1));
}
__device__ __forceinline__ void cpasync16(unsigned dst, const void* src) {
    asm volatile("cp.async.cg.shared.global [%0], [%1], 16;"
                 :: "r"(dst), "l"(src) : "memory");
}

// ------------------ kernel 1: W -> fp16 ------------------
__global__ void prep_W_kernel(const float* __restrict__ W) {
    int idx = blockIdx.x * 256 + threadIdx.x;
    if (idx >= JPAD * KPAD) return;
    int j = idx / KPAD;
    int c = idx - j * KPAD;
    float v = (j < JDIM && c < KTOT) ? W[(size_t)j * KTOT + c] : 0.0f;
    g_Wh[idx] = __float2half_rn(v);
}

// ------------------------- main GEMM kernel -------------------------
__global__ __launch_bounds__(THREADS, 4)
void mma_kernel(const float* __restrict__ x, const float* __restrict__ seeds,
                const float* __restrict__ bias, float* __restrict__ out)
{
    extern __shared__ char smem[];
    const unsigned sb = s2u(smem);
    const int tid  = threadIdx.x;
    const int lane = tid & 31;
    const int warp = tid >> 5;            // 4 warps
    const int mb   = warp >> 1;           // m-band: rows 16mb..16mb+15
    const int nh   = warp & 1;            // n-half: cols 32nh..32nh+31
    const int row0 = blockIdx.x * MT;

    // ldmatrix lane geometry
    const int amat  = lane >> 3;
    const int arow  = 16 * mb + 8 * (amat & 1) + (lane & 7);
    const int acolb = (amat >> 1) * 16;              // byte offset within k16
    const int brow  = (lane & 7);
    const int bnt   = (lane >> 4) & 1;               // ntile within pair
    const int bkb   = ((lane >> 3) & 1) * 16;        // byte k-offset

    // x tile = 32 rows x 32 float4 = 1024 float4; 8 iters of 128 thr.
    const int xrw = tid >> 5;             // base row (0..3); row_i = xrw + 4i
    const int xq  = tid & 31;             // float4-col 0..31
    const int xkb = xq >> 4;              // k-block of this thread's column
    const int xq64 = xq & 15;
    // W tile per k-block = 64 j x 8 slots of 16B = 512; 4 iters of 128 thr
    const int wj[4] = { tid >> 3, (tid + 128) >> 3, (tid + 256) >> 3, (tid + 384) >> 3 };
    const int wqq = tid & 7;

    float acc[4][4];
    #pragma unroll
    for (int n = 0; n < 4; n++)
        #pragma unroll
        for (int q = 0; q < 4; q++) acc[n][q] = 0.0f;

    float4 xr[8];

    #define LOADX(ch) { _Pragma("unroll") \
        for (int i = 0; i < 8; i++) \
            xr[i] = *reinterpret_cast<const float4*>( \
                x + (size_t)(row0 + xrw + 4 * i) * KX + (ch) * 128 + 4 * xq); }
    #define CPW(ch, s) { _Pragma("unroll") \
        for (int kb = 0; kb < 2; kb++) { \
            _Pragma("unroll") \
            for (int i = 0; i < 4; i++) { \
                const unsigned so = (unsigned)(kb * B_SUB) + swz((unsigned)(wj[i] * 128 + 16 * wqq)); \
                cpasync16(sb + OFF_B(s) + so, \
                          &g_Wh[(size_t)wj[i] * KPAD + (ch) * 128 + kb * 64 + 8 * wqq]); \
            } \
        } \
        asm volatile("cp.async.commit_group;" ::: "memory"); }
    #define STSX(s) { _Pragma("unroll") \
        for (int i = 0; i < 8; i++) { \
            const float4 v = xr[i]; \
            const unsigned off = (unsigned)(xkb * A_SUB) + \
                swz((unsigned)((xrw + 4 * i) * 128 + 8 * xq64)); \
            const unsigned long long pp = (unsigned long long)pack_h(v.x, v.y) | \
                ((unsigned long long)pack_h(v.z, v.w) << 32); \
            *reinterpret_cast<unsigned long long*>(smem + OFF_A(s) + off) = pp; } }

    #define COMPUTE(s) { \
        const unsigned aB = sb + OFF_A(s); \
        const unsigned bB = sb + OFF_B(s); \
        _Pragma("unroll") \
        for (int kk = 0; kk < 8; kk++) { \
            const int kb = kk >> 2, kl = kk & 3; \
            const unsigned aoff = (unsigned)(kb * A_SUB) + \
                swz((unsigned)(arow * 128 + 32 * kl + acolb)); \
            unsigned a0, a1, a2, a3; \
            ldsm4(aB + aoff, a0, a1, a2, a3); \
            _Pragma("unroll") \
            for (int ntp = 0; ntp < 2; ntp++) { \
                const unsigned boff = (unsigned)(kb * B_SUB) + swz((unsigned)( \
                    (8 * (4 * nh + 2 * ntp + bnt) + brow) * 128 + 32 * kl + bkb)); \
                unsigned b0, b1, b2, b3; \
                ldsm4(bB + boff, b0, b1, b2, b3); \
                mmaf16(acc[2 * ntp],     a0, a1, a2, a3, b0, b1); \
                mmaf16(acc[2 * ntp + 1], a0, a1, a2, a3, b2, b3); \
            } \
        } }

    // ---------------- pipeline: 1 sync per chunk, ping-pong stages ----------------
    CPW(0, 0);
    LOADX(0);

    for (int ch = 0; ch < NCH; ch++) {
        const int s = ch & 1;
        STSX(s);                                           // x(ch) -> stage s
        asm volatile("cp.async.wait_group 0;" ::: "memory");  // W(ch) arrived
        __syncthreads();                                   // stage s ready; s^1 free
        CPW(ch + 1, s ^ 1);                                // W(ch+1) async
        if (ch + 1 < NCH) LOADX(ch + 1);                   // x(ch+1) -> regs
        COMPUTE(s);
    }

    // ---- seeds chunk (ch = 25 -> stage 1; loop's last CPW targeted stage 1) ----
    for (int i = tid; i < A_BYTES / 16; i += THREADS)
        *reinterpret_cast<uint4*>(smem + OFF_A(1) + 16 * i) = make_uint4(0, 0, 0, 0);
    __syncthreads();                                       // zeros visible
    for (int i = tid; i < MT * KS; i += THREADS) {
        const int r = i / KS, c = i - r * KS;
        const float v = seeds[(size_t)(row0 + r) * KS + c];
        const unsigned off = swz((unsigned)(r * 128 + 2 * c));   // kb 0 (c < 64)
        *reinterpret_cast<__half*>(smem + OFF_A(1) + off) = __float2half_rn(v);
    }
    asm volatile("cp.async.wait_group 0;" ::: "memory");   // W(seeds) arrived
    __syncthreads();
    COMPUTE(1);

    // ---- epilogue: frags -> smem -> permuted+bias store ----
    __syncthreads();                                       // all computes done
    float* red = reinterpret_cast<float*>(smem);           // [32][68]
    const int g = lane >> 2, t = lane & 3;
    #pragma unroll
    for (int nt = 0; nt < 4; nt++) {
        const int col = 32 * nh + 8 * nt + 2 * t;
        red[(16 * mb + g)     * 68 + col]     = acc[nt][0];
        red[(16 * mb + g)     * 68 + col + 1] = acc[nt][1];
        red[(16 * mb + 8 + g) * 68 + col]     = acc[nt][2];
        red[(16 * mb + 8 + g) * 68 + col + 1] = acc[nt][3];
    }
    __syncthreads();
    for (int i = tid; i < MT * JDIM; i += THREADS) {
        const int r = i / JDIM, pos = i - r * JDIM;
        const int o = pos / 20, node = pos - 20 * o;
        const int j = node * 3 + o;
        out[(size_t)row0 * JDIM + i] = red[r * 68 + j] + bias[j];
    }
}

extern "C" void kernel_launch(void* const* d_in, const int* in_sizes, int n_in,
                              void* d_out, int out_size)
{
    const float* x     = (const float*)d_in[0];
    const float* seeds = (const float*)d_in[1];
    const float* W     = (const float*)d_in[2];
    const float* b     = (const float*)d_in[3];
    float*       out   = (float*)d_out;

    cudaFuncSetAttribute(mma_kernel,
                         cudaFuncAttributeMaxDynamicSharedMemorySize, SMEM_SZ);
    prep_W_kernel<<<(JPAD * KPAD + 255) / 256, 256>>>(W);
    mma_kernel<<<NROWS / MT, THREADS, SMEM_SZ>>>(x, seeds, b, out);
}

// round 15
// speedup vs baseline: 8.1493x; 1.0361x over previous
#include <cuda_runtime.h>
#include <cuda_fp16.h>

// GenerateNodes via pure-fp16 mma.sync (HMMA) GEMM — compute_103-safe.
//   out[m, o*20+node] = sum_c mix[m,c] * W[node*3+o, c] + b[node*3+o]
//   mix = concat(x[m,0:3200], seeds[m,0:15]);
//   A = fp16(mix), W = fp16(W), fp32 accumulate. rel_err ~3e-4 (<1e-3).
// R14: k-split warp tiling — 4 warps = 2 k-halves x 2 n-halves, each 32x32.
//      B ldsm redundancy eliminated (-33% ldsm traffic). MT=32, 4 CTAs/SM.

#define NROWS   16384
#define KX      3200
#define KS      15
#define KTOT    3215
#define KPAD    3328      // 26 * 128
#define NCH     25        // full x chunks of 128; chunk 25 = seeds
#define JDIM    60
#define JPAD    64
#define MT      32        // rows per CTA
#define THREADS 128

#define A_SUB   4096              // 32 rows x 64 fp16 (128 B, SW128)
#define B_SUB   8192              // 64 j x 64 fp16
#define A_BYTES (2 * A_SUB)       // 8192  (2 k-blocks)
#define B_BYTES (2 * B_SUB)       // 16384
#define STG     (A_BYTES + B_BYTES)       // 24576 per stage
#define OFF_A(s)  ((s) * STG)
#define OFF_B(s)  ((s) * STG + A_BYTES)
#define SMEM_SZ   (2 * STG)       // 49152 bytes

__device__ __align__(16) __half g_Wh[JPAD * KPAD];

// ------------------------- helpers -------------------------
__device__ __forceinline__ unsigned s2u(const void* p) {
    unsigned a;
    asm("{ .reg .u64 t; cvta.to.shared.u64 t, %1; cvt.u32.u64 %0, t; }"
        : "=r"(a) : "l"(p));
    return a;
}
__device__ __forceinline__ unsigned swz(unsigned off) {
    return off ^ ((off >> 3) & 0x70);
}
__device__ __forceinline__ unsigned pack_h(float a, float b) {
    unsigned short ra = __half_as_ushort(__float2half_rn(a));
    unsigned short rb = __half_as_ushort(__float2half_rn(b));
    return (unsigned)ra | ((unsigned)rb << 16);
}
__device__ __forceinline__ void ldsm4(unsigned addr, unsigned& r0, unsigned& r1,
                                      unsigned& r2, unsigned& r3) {
    asm volatile("ldmatrix.sync.aligned.m8n8.x4.shared.b16 {%0,%1,%2,%3}, [%4];"
                 : "=r"(r0), "=r"(r1), "=r"(r2), "=r"(r3) : "r"(addr));
}
__device__ __forceinline__ void mmaf16(float* c, unsigned a0, unsigned a1,
                                       unsigned a2, unsigned a3,
                                       unsigned b0, unsigned b1) {
    asm volatile(
        "mma.sync.aligned.m16n8k16.row.col.f32.f16.f16.f32 "
        "{%0,%1,%2,%3}, {%4,%5,%6,%7}, {%8,%9}, {%0,%1,%2,%3};"
        : "+f"(c[0]), "+f"(c[1]), "+f"(c[2]), "+f"(c[3])
        : "r"(a0), "r"(a1), "r"(a2), "r"(a3), "r"(b0), "r"(b1));
}
__device__ __forceinline__ void cpasync16(unsigned dst, const void* src) {
    asm volatile("cp.async.cg.shared.global [%0], [%1], 16;"
                 :: "r"(dst), "l"(src) : "memory");
}

// ------------------ kernel 1: W -> fp16 ------------------
__global__ void prep_W_kernel(const float* __restrict__ W) {
    int idx = blockIdx.x * 256 + threadIdx.x;
    if (idx >= JPAD * KPAD) return;
    int j = idx / KPAD;
    int c = idx - j * KPAD;
    float v = (j < JDIM && c < KTOT) ? W[(size_t)j * KTOT + c] : 0.0f;
    g_Wh[idx] = __float2half_rn(v);
}

// ------------------------- main GEMM kernel -------------------------
__global__ __launch_bounds__(THREADS, 4)
void mma_kernel(const float* __restrict__ x, const float* __restrict__ seeds,
                const float* __restrict__ bias, float* __restrict__ out)
{
    extern __shared__ char smem[];
    const unsigned sb = s2u(smem);
    const int tid  = threadIdx.x;
    const int lane = tid & 31;
    const int warp = tid >> 5;            // 4 warps
    const int kh   = warp >> 1;           // k-half: kb sub-tile kh
    const int nh   = warp & 1;            // n-half: cols 32nh..32nh+31
    const int row0 = blockIdx.x * MT;

    // ldmatrix lane geometry (A covers rows 0..31 via mb loop)
    const int amat  = lane >> 3;
    const int arow0 = 8 * (amat & 1) + (lane & 7);   // + 16*mb
    const int acolb = (amat >> 1) * 16;              // byte offset within k16
    const int brow  = (lane & 7);
    const int bnt   = (lane >> 4) & 1;               // ntile within pair
    const int bkb   = ((lane >> 3) & 1) * 16;        // byte k-offset

    // x tile = 32 rows x 32 float4 = 1024 float4; 8 iters of 128 thr.
    const int xrw = tid >> 5;             // base row (0..3); row_i = xrw + 4i
    const int xq  = tid & 31;             // float4-col 0..31
    const int xkb = xq >> 4;              // k-block of this thread's column
    const int xq64 = xq & 15;
    // W tile per k-block = 64 j x 8 slots of 16B = 512; 4 iters of 128 thr
    const int wj[4] = { tid >> 3, (tid + 128) >> 3, (tid + 256) >> 3, (tid + 384) >> 3 };
    const int wqq = tid & 7;

    // acc[4*mb + nt][4]: mb in {0,1} row-band, nt in {0..3} n8-tile
    float acc[8][4];
    #pragma unroll
    for (int n = 0; n < 8; n++)
        #pragma unroll
        for (int q = 0; q < 4; q++) acc[n][q] = 0.0f;

    float4 xr[8];

    #define LOADX(ch) { _Pragma("unroll") \
        for (int i = 0; i < 8; i++) \
            xr[i] = *reinterpret_cast<const float4*>( \
                x + (size_t)(row0 + xrw + 4 * i) * KX + (ch) * 128 + 4 * xq); }
    #define CPW(ch, s) { _Pragma("unroll") \
        for (int kb = 0; kb < 2; kb++) { \
            _Pragma("unroll") \
            for (int i = 0; i < 4; i++) { \
                const unsigned so = (unsigned)(kb * B_SUB) + swz((unsigned)(wj[i] * 128 + 16 * wqq)); \
                cpasync16(sb + OFF_B(s) + so, \
                          &g_Wh[(size_t)wj[i] * KPAD + (ch) * 128 + kb * 64 + 8 * wqq]); \
            } \
        } \
        asm volatile("cp.async.commit_group;" ::: "memory"); }
    #define STSX(s) { _Pragma("unroll") \
        for (int i = 0; i < 8; i++) { \
            const float4 v = xr[i]; \
            const unsigned off = (unsigned)(xkb * A_SUB) + \
                swz((unsigned)((xrw + 4 * i) * 128 + 8 * xq64)); \
            const unsigned long long pp = (unsigned long long)pack_h(v.x, v.y) | \
                ((unsigned long long)pack_h(v.z, v.w) << 32); \
            *reinterpret_cast<unsigned long long*>(smem + OFF_A(s) + off) = pp; } }

    // Each warp: its kh sub-tile only; rows 0..31 (mb loop), cols 32nh..+31.
    #define COMPUTE(s) { \
        const unsigned aB = sb + OFF_A(s) + (unsigned)(kh * A_SUB); \
        const unsigned bB = sb + OFF_B(s) + (unsigned)(kh * B_SUB); \
        _Pragma("unroll") \
        for (int kl = 0; kl < 4; kl++) { \
            unsigned a0[2][4]; \
            _Pragma("unroll") \
            for (int mb = 0; mb < 2; mb++) { \
                const unsigned aoff = swz((unsigned)( \
                    (16 * mb + arow0) * 128 + 32 * kl + acolb)); \
                ldsm4(aB + aoff, a0[mb][0], a0[mb][1], a0[mb][2], a0[mb][3]); \
            } \
            _Pragma("unroll") \
            for (int ntp = 0; ntp < 2; ntp++) { \
                const unsigned boff = swz((unsigned)( \
                    (8 * (4 * nh + 2 * ntp + bnt) + brow) * 128 + 32 * kl + bkb)); \
                unsigned b0, b1, b2, b3; \
                ldsm4(bB + boff, b0, b1, b2, b3); \
                _Pragma("unroll") \
                for (int mb = 0; mb < 2; mb++) { \
                    mmaf16(acc[4 * mb + 2 * ntp],     a0[mb][0], a0[mb][1], a0[mb][2], a0[mb][3], b0, b1); \
                    mmaf16(acc[4 * mb + 2 * ntp + 1], a0[mb][0], a0[mb][1], a0[mb][2], a0[mb][3], b2, b3); \
                } \
            } \
        } }

    // ---------------- pipeline: 1 sync per chunk, ping-pong stages ----------------
    CPW(0, 0);
    LOADX(0);

    for (int ch = 0; ch < NCH; ch++) {
        const int s = ch & 1;
        STSX(s);                                           // x(ch) -> stage s
        asm volatile("cp.async.wait_group 0;" ::: "memory");  // W(ch) arrived
        __syncthreads();                                   // stage s ready; s^1 free
        CPW(ch + 1, s ^ 1);                                // W(ch+1) async
        if (ch + 1 < NCH) LOADX(ch + 1);                   // x(ch+1) -> regs
        COMPUTE(s);
    }

    // ---- seeds chunk (ch = 25 -> stage 1; loop's last CPW targeted stage 1) ----
    for (int i = tid; i < A_BYTES / 16; i += THREADS)
        *reinterpret_cast<uint4*>(smem + OFF_A(1) + 16 * i) = make_uint4(0, 0, 0, 0);
    __syncthreads();                                       // zeros visible
    for (int i = tid; i < MT * KS; i += THREADS) {
        const int r = i / KS, c = i - r * KS;
        const float v = seeds[(size_t)(row0 + r) * KS + c];
        const unsigned off = swz((unsigned)(r * 128 + 2 * c));   // kb 0 (c < 64)
        *reinterpret_cast<__half*>(smem + OFF_A(1) + off) = __float2half_rn(v);
    }
    asm volatile("cp.async.wait_group 0;" ::: "memory");   // W(seeds) arrived
    __syncthreads();
    COMPUTE(1);
    // (kh=1 warps multiply the zeroed kb=1 sub-tiles: harmless.)

    // ---- epilogue: deterministic k-reduction, then permuted+bias store ----
    __syncthreads();                                       // all computes done
    float* red = reinterpret_cast<float*>(smem);           // [32][68]
    const int g = lane >> 2, t = lane & 3;
    if (kh == 0) {
        #pragma unroll
        for (int mb = 0; mb < 2; mb++)
            #pragma unroll
            for (int nt = 0; nt < 4; nt++) {
                const int col = 32 * nh + 8 * nt + 2 * t;
                red[(16 * mb + g)     * 68 + col]     = acc[4 * mb + nt][0];
                red[(16 * mb + g)     * 68 + col + 1] = acc[4 * mb + nt][1];
                red[(16 * mb + 8 + g) * 68 + col]     = acc[4 * mb + nt][2];
                red[(16 * mb + 8 + g) * 68 + col + 1] = acc[4 * mb + nt][3];
            }
    }
    __syncthreads();
    if (kh == 1) {
        #pragma unroll
        for (int mb = 0; mb < 2; mb++)
            #pragma unroll
            for (int nt = 0; nt < 4; nt++) {
                const int col = 32 * nh + 8 * nt + 2 * t;
                red[(16 * mb + g)     * 68 + col]     += acc[4 * mb + nt][0];
                red[(16 * mb + g)     * 68 + col + 1] += acc[4 * mb + nt][1];
                red[(16 * mb + 8 + g) * 68 + col]     += acc[4 * mb + nt][2];
                red[(16 * mb + 8 + g) * 68 + col + 1] += acc[4 * mb + nt][3];
            }
    }
    __syncthreads();
    for (int i = tid; i < MT * JDIM; i += THREADS) {
        const int r = i / JDIM, pos = i - r * JDIM;
        const int o = pos / 20, node = pos - 20 * o;
        const int j = node * 3 + o;
        out[(size_t)row0 * JDIM + i] = red[r * 68 + j] + bias[j];
    }
}

extern "C" void kernel_launch(void* const* d_in, const int* in_sizes, int n_in,
                              void* d_out, int out_size)
{
    const float* x     = (const float*)d_in[0];
    const float* seeds = (const float*)d_in[1];
    const float* W     = (const float*)d_in[2];
    const float* b     = (const float*)d_in[3];
    float*       out   = (float*)d_out;

    cudaFuncSetAttribute(mma_kernel,
                         cudaFuncAttributeMaxDynamicSharedMemorySize, SMEM_SZ);
    prep_W_kernel<<<(JPAD * KPAD + 255) / 256, 256>>>(W);
    mma_kernel<<<NROWS / MT, THREADS, SMEM_SZ>>>(x, seeds, b, out);
}